// round 6
// baseline (speedup 1.0000x reference)
#include <cuda_runtime.h>
#include <cstdint>

typedef unsigned long long ull;

// SimpleGRU — f32x2 packed-FMA persistent kernel.
// lanes = hidden units: thread u (0..255) owns unit u, all 3 gates, all 32
// batches (packed in pairs -> 48 x 64b accumulators). h stored batch-pair-
// packed [k][bp]; W staged per-kb via cp.async; decoder state in registers.

#define HDIM     256
#define THREE_H  768
#define SEQ      64
#define TB       32
#define NTHREADS 256
#define KB       8
#define NKB      32          // 256 / KB
#define WROWF    12          // staged W row: 8 data floats + 4 pad (48B)
#define WSTAGEF  (THREE_H * WROWF)   // 9216 floats per stage buffer
#define UPAD     18          // h row stride in u64 elems (16 data + 2 pad)

// shared-memory byte offsets (all 16B aligned)
#define OFF_HS0  0                  // h buffer 0: 256*18*8 = 36864
#define OFF_HS1  36864              // h buffer 1
#define OFF_WST  73728              // 2 * 36864 W stages (decoder: redu overlay)
#define OFF_RED2 106624             // decoder stage-2: 16*16 u64 = 2048
#define OFF_US   147456             // w_ih col   [768] f32
#define OFF_BIH  150528             // b_ih       [768]
#define OFF_BHH  153600             // b_hh       [768]
#define OFF_WOUT 156672             // w_out      [256]
#define OFF_XS   157696             // x tile     [64][32] f32
#define OFF_OUTS 165888             // decoder outs [32] f32 + b_out
#define SMEM_BYTES 166144

__device__ __forceinline__ ull fma2(ull a, ull b, ull c) {
    ull d; asm("fma.rn.f32x2 %0, %1, %2, %3;" : "=l"(d) : "l"(a), "l"(b), "l"(c));
    return d;
}
__device__ __forceinline__ ull add2(ull a, ull b) {
    ull d; asm("add.rn.f32x2 %0, %1, %2;" : "=l"(d) : "l"(a), "l"(b));
    return d;
}
__device__ __forceinline__ ull mul2(ull a, ull b) {
    ull d; asm("mul.rn.f32x2 %0, %1, %2;" : "=l"(d) : "l"(a), "l"(b));
    return d;
}
__device__ __forceinline__ ull packdup(float x) {
    ull d; asm("mov.b64 %0, {%1, %1};" : "=l"(d) : "f"(x));
    return d;
}
__device__ __forceinline__ ull pack2(float lo, float hi) {
    ull d; asm("mov.b64 %0, {%1, %2};" : "=l"(d) : "f"(lo), "f"(hi));
    return d;
}
__device__ __forceinline__ void unpack2(ull v, float& lo, float& hi) {
    asm("mov.b64 {%0, %1}, %2;" : "=f"(lo), "=f"(hi) : "l"(v));
}
__device__ __forceinline__ float sigf(float v) {
    return __fdividef(1.0f, 1.0f + __expf(-v));
}
__device__ __forceinline__ float tanhf2(float v) {
    return fmaf(2.0f, sigf(2.0f * v), -1.0f);
}

// stage w_hh[:, kb*8 .. kb*8+7] -> [768][WROWF] tile (1536 16B chunks, 6/thread)
__device__ __forceinline__ void stage_kb(const float* __restrict__ w_hh,
                                         float* __restrict__ wst, int kb, int tid) {
#pragma unroll
    for (int r = 0; r < 6; r++) {
        int ch  = tid + r * NTHREADS;     // 0..1535
        int row = ch >> 1;
        int hf  = ch & 1;
        const float* src = w_hh + row * HDIM + kb * KB + hf * 4;
        unsigned d = (unsigned)__cvta_generic_to_shared(wst + row * WROWF + hf * 4);
        asm volatile("cp.async.cg.shared.global [%0], [%1], 16;\n" :: "r"(d), "l"(src));
    }
    asm volatile("cp.async.commit_group;\n");
}

// acc[g][bp] += sum_k w_hh[g*256+tid][k] * (h[k][2bp], h[k][2bp+1])
__device__ __forceinline__ void gemm_step(const float* __restrict__ w_hh,
                                          char* smem, const ull* __restrict__ hs,
                                          int tid, ull (&acc)[3][16]) {
    float* wst = (float*)(smem + OFF_WST);
#pragma unroll
    for (int g = 0; g < 3; g++)
#pragma unroll
        for (int bp = 0; bp < 16; bp++) acc[g][bp] = 0ull;

    stage_kb(w_hh, wst, 0, tid);

#pragma unroll 1
    for (int kb = 0; kb < NKB; kb++) {
        asm volatile("cp.async.wait_group 0;\n");
        __syncthreads();                       // all staged chunks visible
        if (kb + 1 < NKB)
            stage_kb(w_hh, wst + ((kb + 1) & 1) * WSTAGEF, kb + 1, tid);

        const float* w0 = wst + (kb & 1) * WSTAGEF + tid * WROWF;
#pragma unroll
        for (int kc = 0; kc < 2; kc++) {
            float wa[3][4];
            *(float4*)wa[0] = *(const float4*)(w0 + kc * 4);
            *(float4*)wa[1] = *(const float4*)(w0 + 256 * WROWF + kc * 4);
            *(float4*)wa[2] = *(const float4*)(w0 + 512 * WROWF + kc * 4);
#pragma unroll
            for (int kk = 0; kk < 4; kk++) {
                const ull* hrow = hs + (kb * KB + kc * 4 + kk) * UPAD;
                ull h2[16];
#pragma unroll
                for (int q = 0; q < 8; q++) {
                    ulonglong2 t2 = ((const ulonglong2*)hrow)[q];
                    h2[2 * q] = t2.x; h2[2 * q + 1] = t2.y;
                }
                ull w2r = packdup(wa[0][kk]);
                ull w2z = packdup(wa[1][kk]);
                ull w2n = packdup(wa[2][kk]);
#pragma unroll
                for (int bp = 0; bp < 16; bp++) {
                    acc[0][bp] = fma2(w2r, h2[bp], acc[0][bp]);
                    acc[1][bp] = fma2(w2z, h2[bp], acc[1][bp]);
                    acc[2][bp] = fma2(w2n, h2[bp], acc[2][bp]);
                }
            }
        }
    }
}

__global__ __launch_bounds__(NTHREADS, 1)
void gru_kernel(const float* __restrict__ gx, const float* __restrict__ w_ih,
                const float* __restrict__ w_hh, const float* __restrict__ b_ih,
                const float* __restrict__ b_hh, const float* __restrict__ w_out,
                const float* __restrict__ b_out, float* __restrict__ out, int TL) {
    extern __shared__ char smem[];
    const int tid = threadIdx.x;
    const int gb0 = blockIdx.x * TB;

    float* usf   = (float*)(smem + OFF_US);
    float* bihf  = (float*)(smem + OFF_BIH);
    float* bhhf  = (float*)(smem + OFF_BHH);
    float* woutf = (float*)(smem + OFF_WOUT);
    float* xs    = (float*)(smem + OFF_XS);
    float* outsf = (float*)(smem + OFF_OUTS);
    ull*   hsA   = (ull*)(smem + OFF_HS0);
    ull*   hsB   = (ull*)(smem + OFF_HS1);

    // ---- init: params, x tile, zero h buffer A ----
    for (int i = tid; i < THREE_H; i += NTHREADS) {
        usf[i]  = w_ih[i];
        bihf[i] = b_ih[i];
        bhhf[i] = b_hh[i];
    }
    for (int i = tid; i < HDIM; i += NTHREADS) woutf[i] = w_out[i];
    for (int i = tid; i < TB * SEQ; i += NTHREADS) {
        int b = i & 31, t = i >> 5;
        xs[t * 32 + b] = gx[(gb0 + b) * SEQ + t];
    }
#pragma unroll
    for (int q = 0; q < UPAD; q++) hsA[q * 256 + tid] = 0ull;
    if (tid == 0) outsf[32] = b_out[0];
    __syncthreads();

    // hoisted per-unit gate params
    const float u_r = usf[tid], u_z = usf[tid + 256], u_n = usf[tid + 512];
    const float bihr = bihf[tid], bihz = bihf[tid + 256], bihn = bihf[tid + 512];
    const float bhhr = bhhf[tid], bhhz = bhhf[tid + 256], bhhn = bhhf[tid + 512];
    const float ebr = bihr + bhhr, ebz = bihz + bhhz;

    ull acc[3][16];

    // ---- encoder: 64 steps ----
#pragma unroll 1
    for (int t = 0; t < SEQ; t++) {
        const ull* hrd = (t & 1) ? hsB : hsA;
        ull*       hwr = (t & 1) ? hsA : hsB;
        gemm_step(w_hh, smem, hrd, tid, acc);

        const ulonglong2* hold = (const ulonglong2*)(hrd + tid * UPAD);
        ulonglong2*       hdst = (ulonglong2*)(hwr + tid * UPAD);
        const float*      xrow = xs + t * 32;
#pragma unroll
        for (int q = 0; q < 8; q++) {
            ulonglong2 ho = hold[q];
            ulonglong2 st;
#pragma unroll
            for (int e2 = 0; e2 < 2; e2++) {
                int bp = 2 * q + e2;
                float ar0, ar1, az0, az1, an0, an1, h0, h1;
                unpack2(acc[0][bp], ar0, ar1);
                unpack2(acc[1][bp], az0, az1);
                unpack2(acc[2][bp], an0, an1);
                unpack2(e2 ? ho.y : ho.x, h0, h1);
                float x0 = xrow[2 * bp], x1 = xrow[2 * bp + 1];
                float r0 = sigf(fmaf(x0, u_r, ebr) + ar0);
                float r1 = sigf(fmaf(x1, u_r, ebr) + ar1);
                float z0 = sigf(fmaf(x0, u_z, ebz) + az0);
                float z1 = sigf(fmaf(x1, u_z, ebz) + az1);
                float n0 = tanhf2(fmaf(x0, u_n, bihn) + r0 * (an0 + bhhn));
                float n1 = tanhf2(fmaf(x1, u_n, bihn) + r1 * (an1 + bhhn));
                float hn0 = fmaf(z0, h0 - n0, n0);
                float hn1 = fmaf(z1, h1 - n1, n1);
                if (e2) st.y = pack2(hn0, hn1); else st.x = pack2(hn0, hn1);
            }
            hdst[q] = st;
        }
        // next gemm's first barrier orders these writes before reads
    }
    // hidden lives in hsA (SEQ even)

    // ---- gh_dec = w_hh @ hidden + b_hh (registers) ----
    gemm_step(w_hh, smem, hsA, tid, acc);
    {
        ull br2 = packdup(bhhr), bz2 = packdup(bhhz), bn2 = packdup(bhhn);
#pragma unroll
        for (int bp = 0; bp < 16; bp++) {
            acc[0][bp] = add2(acc[0][bp], br2);
            acc[1][bp] = add2(acc[1][bp], bz2);
            acc[2][bp] = add2(acc[2][bp], bn2);
        }
    }
    // hidden + rolling h_t in registers
    ull hid2[16], ht2[16];
    {
        const ulonglong2* hr = (const ulonglong2*)(hsA + tid * UPAD);
#pragma unroll
        for (int q = 0; q < 8; q++) {
            ulonglong2 v = hr[q];
            hid2[2 * q] = v.x; hid2[2 * q + 1] = v.y;
            ht2[2 * q] = v.x;  ht2[2 * q + 1] = v.y;
        }
    }
    const ull w2o = packdup(woutf[tid]);
    ull* redu = (ull*)(smem + OFF_WST);      // [16][257] overlay on W stages
    ull* red2 = (ull*)(smem + OFF_RED2);     // [16][16]
    __syncthreads();    // W stages fully consumed before redu overlay

    // ---- decoder: TL steps, h_t in registers ----
#pragma unroll 1
    for (int t = 0; t < TL; t++) {
        // stage 1: per-unit products
#pragma unroll
        for (int bp = 0; bp < 16; bp++)
            redu[bp * 257 + tid] = mul2(w2o, ht2[bp]);
        __syncthreads();
        // stage 2: 16-way partial sums
        {
            int bp = tid >> 4, seg = tid & 15;
            ull s = 0ull;
#pragma unroll
            for (int j = 0; j < 16; j++)
                s = add2(s, redu[bp * 257 + seg * 16 + j]);
            red2[bp * 16 + seg] = s;
        }
        __syncthreads();
        // stage 3: final sums + emit
        if (tid < 16) {
            ull s = 0ull;
#pragma unroll
            for (int j = 0; j < 16; j++) s = add2(s, red2[tid * 16 + j]);
            float lo, hi;
            unpack2(s, lo, hi);
            float bo = outsf[32];
            lo += bo; hi += bo;
            outsf[2 * tid] = lo; outsf[2 * tid + 1] = hi;
            out[(gb0 + 2 * tid) * TL + t] = lo;
            out[(gb0 + 2 * tid + 1) * TL + t] = hi;
        }
        __syncthreads();
        // gate update: h_{t+1} = gru_cell(out, hidden), gh fixed in acc
#pragma unroll
        for (int bp = 0; bp < 16; bp++) {
            float ar0, ar1, az0, az1, an0, an1, h0, h1;
            unpack2(acc[0][bp], ar0, ar1);
            unpack2(acc[1][bp], az0, az1);
            unpack2(acc[2][bp], an0, an1);
            unpack2(hid2[bp], h0, h1);
            float x0 = outsf[2 * bp], x1 = outsf[2 * bp + 1];
            float r0 = sigf(fmaf(x0, u_r, bihr) + ar0);
            float r1 = sigf(fmaf(x1, u_r, bihr) + ar1);
            float z0 = sigf(fmaf(x0, u_z, bihz) + az0);
            float z1 = sigf(fmaf(x1, u_z, bihz) + az1);
            float n0 = tanhf2(fmaf(x0, u_n, bihn) + r0 * an0);
            float n1 = tanhf2(fmaf(x1, u_n, bihn) + r1 * an1);
            ht2[bp] = pack2(fmaf(z0, h0 - n0, n0), fmaf(z1, h1 - n1, n1));
        }
    }
}

extern "C" void kernel_launch(void* const* d_in, const int* in_sizes, int n_in,
                              void* d_out, int out_size) {
    const float* x     = (const float*)d_in[0];
    const float* w_ih  = (const float*)d_in[1];
    const float* w_hh  = (const float*)d_in[2];
    const float* b_ih  = (const float*)d_in[3];
    const float* b_hh  = (const float*)d_in[4];
    const float* w_out = (const float*)d_in[5];
    const float* b_out = (const float*)d_in[6];
    float* out = (float*)d_out;

    int B  = in_sizes[0] / SEQ;
    int TL = out_size / B;

    cudaFuncSetAttribute(gru_kernel, cudaFuncAttributeMaxDynamicSharedMemorySize,
                         SMEM_BYTES);
    gru_kernel<<<B / TB, NTHREADS, SMEM_BYTES>>>(x, w_ih, w_hh, b_ih, b_hh,
                                                 w_out, b_out, out, TL);
}

// round 8
// speedup vs baseline: 2.6541x; 2.6541x over previous
#include <cuda_runtime.h>
#include <cuda_bf16.h>
#include <cstdint>

typedef uint32_t u32;

#define SEQ 64
#define TB  32
#define KCB 49152          // staged bytes per k-chunk (hi+lo images)
#define IMGHALF 24576

__device__ char  g_w[16 * KCB];          // [kc][img][48 tiles][32 thr][16B]
__device__ float g_gh[4096 * 768];
__device__ float g_hid[4096 * 256];

// ---------- FFMA/ALU-pipe activations (no MUFU) ----------
__device__ __forceinline__ float fsig(float x) {
    float z = fminf(fmaxf(-1.44269504f * x, -126.f), 126.f);   // log2(e^-x)
    float fn = z + 12582912.f;                                  // rint magic
    int n = __float_as_int(fn) - 0x4B400000;
    float r = z - (fn - 12582912.f);
    float p = 1.3333558e-3f;
    p = fmaf(p, r, 9.6181291e-3f);
    p = fmaf(p, r, 5.5504109e-2f);
    p = fmaf(p, r, 2.4022651e-1f);
    p = fmaf(p, r, 6.9314718e-1f);
    p = fmaf(p, r, 1.0f);
    float e = __int_as_float(__float_as_int(p) + (n << 23));    // e^-x
    float d = 1.f + e;
    float y = __int_as_float(0x7EF311C3 - __float_as_int(d));   // ~1/d
    y = y * fmaf(-d, y, 2.f);
    y = y * fmaf(-d, y, 2.f);
    y = y * fmaf(-d, y, 2.f);
    return y;
}
__device__ __forceinline__ float ftanh(float v) {
    return fmaf(2.f, fsig(2.f * v), -1.f);
}

__device__ __forceinline__ void mma_b(float* d, const u32* a, const u32* b) {
    asm volatile(
        "mma.sync.aligned.m16n8k16.row.col.f32.bf16.bf16.f32 "
        "{%0,%1,%2,%3}, {%4,%5,%6,%7}, {%8,%9}, {%0,%1,%2,%3};"
        : "+f"(d[0]), "+f"(d[1]), "+f"(d[2]), "+f"(d[3])
        : "r"(a[0]), "r"(a[1]), "r"(a[2]), "r"(a[3]), "r"(b[0]), "r"(b[1]));
}

// ---------- prep: split w_hh to bf16 hi/lo in fragment-direct layout ----------
__global__ void prep_kernel(const float* __restrict__ w_hh) {
    int idx = blockIdx.x * 256 + threadIdx.x;
    if (idx >= 768 * 256) return;
    int row = idx >> 8, col = idx & 255;
    float wv = w_hh[idx];
    __nv_bfloat16 hi = __float2bfloat16(wv);
    __nv_bfloat16 lo = __float2bfloat16(wv - __bfloat162float(hi));
    int kc = col >> 4, ci = col & 15, rt = row >> 4, ri = row & 15;
    int gid = ri & 7, e = ci & 1, tig = (ci >> 1) & 3;
    int reg = (ri >> 3) | (((ci >> 3) & 1) << 1);
    int off = kc * KCB + rt * 512 + (gid * 4 + tig) * 16 + reg * 4 + e * 2;
    *(__nv_bfloat16*)(g_w + off) = hi;
    *(__nv_bfloat16*)(g_w + off + IMGHALF) = lo;
}

// ---------- encoder ----------
// smem: 2 x 49152 stages | hhi 32x264 bf16 | hlo | xs 64x32 f32 | params
#define OFF_HHI 98304
#define OFF_HLO 115200
#define OFF_XS  132096
#define OFF_PU  140288
#define OFF_PBI 143360
#define OFF_PBH 146432
#define SMEM_ENC 149504

__device__ __forceinline__ void stage(char* dst, const char* src, int tid) {
#pragma unroll
    for (int r = 0; r < 12; r++) {
        int off = (tid + r * 256) * 16;
        u32 d = (u32)__cvta_generic_to_shared(dst + off);
        asm volatile("cp.async.cg.shared.global [%0], [%1], 16;"
                     :: "r"(d), "l"(src + off));
    }
    asm volatile("cp.async.commit_group;");
}

__global__ __launch_bounds__(256, 1)
void enc_kernel(const float* __restrict__ gx, const float* __restrict__ w_ih,
                const float* __restrict__ b_ih, const float* __restrict__ b_hh) {
    extern __shared__ char sm[];
    const int tid = threadIdx.x, w = tid >> 5, lane = tid & 31;
    const int gid = lane >> 2, tig = lane & 3;
    const int gb0 = blockIdx.x * TB;
    float* xs  = (float*)(sm + OFF_XS);
    float* pu  = (float*)(sm + OFF_PU);
    float* pbi = (float*)(sm + OFF_PBI);
    float* pbh = (float*)(sm + OFF_PBH);

    for (int i = tid; i < 768; i += 256) {
        pu[i] = w_ih[i]; pbi[i] = b_ih[i]; pbh[i] = b_hh[i];
    }
    for (int i = tid; i < 8448; i += 256) ((u32*)(sm + OFF_HHI))[i] = 0;
    for (int i = tid; i < TB * SEQ; i += 256) {
        int b = i & 31, t = i >> 5;
        xs[t * 32 + b] = gx[(gb0 + b) * SEQ + t];
    }
    __syncthreads();

    float h[2][4][4];
    float acc[3][2][4][4];
#pragma unroll
    for (int i = 0; i < 2; i++)
#pragma unroll
        for (int bt = 0; bt < 4; bt++)
#pragma unroll
            for (int e = 0; e < 4; e++) {
                h[i][bt][e] = 0.f;
                acc[0][i][bt][e] = acc[1][i][bt][e] = acc[2][i][bt][e] = 0.f;
            }

#pragma unroll 1
    for (int step = 0; step <= 64; step++) {
        stage(sm, g_w, tid);
#pragma unroll 1
        for (int kc = 0; kc < 16; kc++) {
            __syncthreads();                      // prev buffer fully consumed
            if (kc < 15) {
                stage(sm + ((kc + 1) & 1) * KCB, g_w + (kc + 1) * KCB, tid);
                asm volatile("cp.async.wait_group 1;");
            } else {
                asm volatile("cp.async.wait_group 0;");
            }
            __syncthreads();                      // current buffer visible

            // B fragments from h (b = bt*8+gid, k pairs at kc*16+tig*2, +8)
            u32 Bh[4][2], Bl[4][2];
#pragma unroll
            for (int bt = 0; bt < 4; bt++) {
                int ha = (bt * 8 + gid) * 528 + kc * 32 + tig * 4;
                Bh[bt][0] = *(u32*)(sm + OFF_HHI + ha);
                Bh[bt][1] = *(u32*)(sm + OFF_HHI + ha + 16);
                Bl[bt][0] = *(u32*)(sm + OFF_HLO + ha);
                Bl[bt][1] = *(u32*)(sm + OFF_HLO + ha + 16);
            }
            const char* cur = sm + (kc & 1) * KCB;
#pragma unroll
            for (int g = 0; g < 3; g++)
#pragma unroll
                for (int i = 0; i < 2; i++) {
                    int rt = g * 16 + w * 2 + i;
                    const char* ab = cur + rt * 512 + lane * 16;
                    uint4 Ah = *(const uint4*)ab;
                    uint4 Al = *(const uint4*)(ab + IMGHALF);
#pragma unroll
                    for (int bt = 0; bt < 4; bt++) {
                        mma_b(acc[g][i][bt], (u32*)&Ah, Bh[bt]);
                        mma_b(acc[g][i][bt], (u32*)&Ah, Bl[bt]);
                        mma_b(acc[g][i][bt], (u32*)&Al, Bh[bt]);
                    }
                }
        }
        __syncthreads();      // all reads of hbuf/stages done before epilogue

        if (step < 64) {
#pragma unroll
            for (int i = 0; i < 2; i++)
#pragma unroll
                for (int bt = 0; bt < 4; bt++)
#pragma unroll
                    for (int eu = 0; eu < 2; eu++)
#pragma unroll
                        for (int eb = 0; eb < 2; eb++) {
                            int di = eu * 2 + eb;
                            int u = w * 32 + i * 16 + gid + eu * 8;
                            int b = bt * 8 + tig * 2 + eb;
                            float x = xs[step * 32 + b];
                            float r = fsig(acc[0][i][bt][di] +
                                           fmaf(x, pu[u], pbi[u] + pbh[u]));
                            float z = fsig(acc[1][i][bt][di] +
                                           fmaf(x, pu[256 + u],
                                                pbi[256 + u] + pbh[256 + u]));
                            float n = ftanh(fmaf(x, pu[512 + u], pbi[512 + u]) +
                                            r * (acc[2][i][bt][di] + pbh[512 + u]));
                            float hn = fmaf(z, h[i][bt][di] - n, n);
                            h[i][bt][di] = hn;
                            __nv_bfloat16 bhi = __float2bfloat16(hn);
                            __nv_bfloat16 blo =
                                __float2bfloat16(hn - __bfloat162float(bhi));
                            int ho = b * 528 + u * 2;
                            *(__nv_bfloat16*)(sm + OFF_HHI + ho) = bhi;
                            *(__nv_bfloat16*)(sm + OFF_HLO + ho) = blo;
                            acc[0][i][bt][di] = 0.f;
                            acc[1][i][bt][di] = 0.f;
                            acc[2][i][bt][di] = 0.f;
                        }
        } else {   // gh_dec: write gh + hidden to scratch
#pragma unroll
            for (int i = 0; i < 2; i++)
#pragma unroll
                for (int bt = 0; bt < 4; bt++)
#pragma unroll
                    for (int eu = 0; eu < 2; eu++)
#pragma unroll
                        for (int eb = 0; eb < 2; eb++) {
                            int di = eu * 2 + eb;
                            int u = w * 32 + i * 16 + gid + eu * 8;
                            int b = bt * 8 + tig * 2 + eb;
                            float* gg = g_gh + (size_t)(gb0 + b) * 768;
                            gg[u]       = acc[0][i][bt][di] + pbh[u];
                            gg[256 + u] = acc[1][i][bt][di] + pbh[256 + u];
                            gg[512 + u] = acc[2][i][bt][di] + pbh[512 + u];
                            g_hid[(size_t)(gb0 + b) * 256 + u] = h[i][bt][di];
                        }
        }
    }
}

// ---------- decoder: TL cheap steps, state in registers ----------
__global__ __launch_bounds__(256, 1)
void dec_kernel(const float* __restrict__ w_ih, const float* __restrict__ b_ih,
                const float* __restrict__ w_out, const float* __restrict__ b_out,
                float* __restrict__ out, int TL) {
    __shared__ float red[32 * 264];
    __shared__ float red2[256];
    __shared__ float outs[32];
    const int u = threadIdx.x;
    const int gb0 = blockIdx.x * 32;
    const float u_r = w_ih[u], u_z = w_ih[256 + u], u_n = w_ih[512 + u];
    const float bir = b_ih[u], biz = b_ih[256 + u], bin = b_ih[512 + u];
    const float wo = w_out[u], bo = b_out[0];

    float ghr[32], ghz[32], ghn[32], hid[32], ht[32];
#pragma unroll
    for (int b = 0; b < 32; b++) {
        const float* gg = g_gh + (size_t)(gb0 + b) * 768;
        ghr[b] = gg[u]; ghz[b] = gg[256 + u]; ghn[b] = gg[512 + u];
        hid[b] = g_hid[(size_t)(gb0 + b) * 256 + u];
        ht[b] = hid[b];
    }
#pragma unroll 1
    for (int t = 0; t < TL; t++) {
#pragma unroll
        for (int b = 0; b < 32; b++) red[b * 264 + u] = wo * ht[b];
        __syncthreads();
        {
            int b2 = u >> 3, seg = u & 7;
            float s = 0.f;
#pragma unroll
            for (int j = 0; j < 32; j++)
                s += red[b2 * 264 + seg * 32 + ((j + seg * 4) & 31)];
            red2[u] = s;
        }
        __syncthreads();
        if (u < 32) {
            float s = 0.f;
#pragma unroll
            for (int j = 0; j < 8; j++) s += red2[u * 8 + j];
            s += bo;
            outs[u] = s;
            out[(size_t)(gb0 + u) * TL + t] = s;
        }
        __syncthreads();
#pragma unroll
        for (int b = 0; b < 32; b++) {
            float x = outs[b];
            float r = fsig(fmaf(x, u_r, bir) + ghr[b]);
            float z = fsig(fmaf(x, u_z, biz) + ghz[b]);
            float n = ftanh(fmaf(x, u_n, bin) + r * ghn[b]);
            ht[b] = fmaf(z, hid[b] - n, n);
        }
        __syncthreads();
    }
}

extern "C" void kernel_launch(void* const* d_in, const int* in_sizes, int n_in,
                              void* d_out, int out_size) {
    const float* x     = (const float*)d_in[0];
    const float* w_ih  = (const float*)d_in[1];
    const float* w_hh  = (const float*)d_in[2];
    const float* b_ih  = (const float*)d_in[3];
    const float* b_hh  = (const float*)d_in[4];
    const float* w_out = (const float*)d_in[5];
    const float* b_out = (const float*)d_in[6];
    float* out = (float*)d_out;

    int B  = in_sizes[0] / SEQ;
    int TL = out_size / B;

    prep_kernel<<<768, 256>>>(w_hh);
    cudaFuncSetAttribute(enc_kernel, cudaFuncAttributeMaxDynamicSharedMemorySize,
                         SMEM_ENC);
    enc_kernel<<<B / TB, 256, SMEM_ENC>>>(x, w_ih, b_ih, b_hh);
    dec_kernel<<<B / 32, 256>>>(w_ih, b_ih, w_out, b_out, out, TL);
}

// round 10
// speedup vs baseline: 3.0789x; 1.1601x over previous
#include <cuda_runtime.h>
#include <cuda_fp16.h>
#include <cstdint>

typedef uint32_t u32;

#define SEQ 64
#define TB  32
#define KCB 49152          // staged bytes per k16-chunk (hi+lo fp16 images)
#define IMGHALF 24576

__device__ char  g_w[16 * KCB];          // [kc][img][48 tiles][32 thr][16B]
__device__ float g_gh[4096 * 768];
__device__ float g_hid[4096 * 256];

// ---------- FFMA/ALU-pipe activations (no MUFU) ----------
__device__ __forceinline__ float fsig(float x) {
    float z = fminf(fmaxf(-1.44269504f * x, -126.f), 126.f);   // log2(e^-x)
    float fn = z + 12582912.f;                                  // rint magic
    int n = __float_as_int(fn) - 0x4B400000;
    float r = z - (fn - 12582912.f);
    float p = 1.3333558e-3f;
    p = fmaf(p, r, 9.6181291e-3f);
    p = fmaf(p, r, 5.5504109e-2f);
    p = fmaf(p, r, 2.4022651e-1f);
    p = fmaf(p, r, 6.9314718e-1f);
    p = fmaf(p, r, 1.0f);
    float e = __int_as_float(__float_as_int(p) + (n << 23));    // e^-x
    float d = 1.f + e;
    float y = __int_as_float(0x7EF311C3 - __float_as_int(d));   // ~1/d
    y = y * fmaf(-d, y, 2.f);
    y = y * fmaf(-d, y, 2.f);
    y = y * fmaf(-d, y, 2.f);
    return y;
}
__device__ __forceinline__ float ftanh(float v) {
    return fmaf(2.f, fsig(2.f * v), -1.f);
}

__device__ __forceinline__ void mma_h(float* d, const u32* a, const u32* b) {
    asm volatile(
        "mma.sync.aligned.m16n8k16.row.col.f32.f16.f16.f32 "
        "{%0,%1,%2,%3}, {%4,%5,%6,%7}, {%8,%9}, {%0,%1,%2,%3};"
        : "+f"(d[0]), "+f"(d[1]), "+f"(d[2]), "+f"(d[3])
        : "r"(a[0]), "r"(a[1]), "r"(a[2]), "r"(a[3]), "r"(b[0]), "r"(b[1]));
}

// ---------- prep: split w_hh to fp16 hi/lo in fragment-direct layout ----------
__global__ void prep_kernel(const float* __restrict__ w_hh) {
    int idx = blockIdx.x * 256 + threadIdx.x;
    if (idx >= 768 * 256) return;
    int row = idx >> 8, col = idx & 255;
    float wv = w_hh[idx];
    __half hi = __float2half_rn(wv);
    __half lo = __float2half_rn(wv - __half2float(hi));
    int kc = col >> 4, ci = col & 15, rt = row >> 4, ri = row & 15;
    int gid = ri & 7, e = ci & 1, tig = (ci >> 1) & 3;
    int reg = (ri >> 3) | (((ci >> 3) & 1) << 1);
    int off = kc * KCB + rt * 512 + (gid * 4 + tig) * 16 + reg * 4 + e * 2;
    *(__half*)(g_w + off) = hi;
    *(__half*)(g_w + off + IMGHALF) = lo;
}

// ---------- encoder ----------
// smem: 3 x 49152 stages | h 32x264 fp16 | xs 64x32 f32 | params
#define OFF_H   147456
#define OFF_XS  164352
#define OFF_PU  172544
#define OFF_PBI 175616
#define OFF_PBH 178688
#define SMEM_ENC 181760

__device__ __forceinline__ void stage(char* dst, const char* src, int tid) {
#pragma unroll
    for (int r = 0; r < 12; r++) {
        int off = (tid + r * 256) * 16;
        u32 d = (u32)__cvta_generic_to_shared(dst + off);
        asm volatile("cp.async.cg.shared.global [%0], [%1], 16;"
                     :: "r"(d), "l"(src + off));
    }
    asm volatile("cp.async.commit_group;");
}

__global__ __launch_bounds__(256, 1)
void enc_kernel(const float* __restrict__ gx, const float* __restrict__ w_ih,
                const float* __restrict__ b_ih, const float* __restrict__ b_hh) {
    extern __shared__ char sm[];
    const int tid = threadIdx.x, w = tid >> 5, lane = tid & 31;
    const int gid = lane >> 2, tig = lane & 3;
    const int gb0 = blockIdx.x * TB;
    float* xs  = (float*)(sm + OFF_XS);
    float* pu  = (float*)(sm + OFF_PU);
    float* pbi = (float*)(sm + OFF_PBI);
    float* pbh = (float*)(sm + OFF_PBH);

    for (int i = tid; i < 768; i += 256) {
        pu[i] = w_ih[i]; pbi[i] = b_ih[i]; pbh[i] = b_hh[i];
    }
    for (int i = tid; i < 4224; i += 256) ((u32*)(sm + OFF_H))[i] = 0;
    for (int i = tid; i < TB * SEQ; i += 256) {
        int b = i & 31, t = i >> 5;
        xs[t * 32 + b] = gx[(gb0 + b) * SEQ + t];
    }
    __syncthreads();

    float h[2][4][4];
    float acc[3][2][4][4];
#pragma unroll
    for (int i = 0; i < 2; i++)
#pragma unroll
        for (int bt = 0; bt < 4; bt++)
#pragma unroll
            for (int e = 0; e < 4; e++) {
                h[i][bt][e] = 0.f;
                acc[0][i][bt][e] = acc[1][i][bt][e] = acc[2][i][bt][e] = 0.f;
            }

#pragma unroll 1
    for (int step = 0; step <= 64; step++) {
        stage(sm, g_w, tid);
        stage(sm + KCB, g_w + KCB, tid);
#pragma unroll 1
        for (int kc = 0; kc < 16; kc++) {
            if (kc < 15) asm volatile("cp.async.wait_group 1;");
            else         asm volatile("cp.async.wait_group 0;");
            __syncthreads();              // chunk kc visible; kc-1 consumed by all
            if (kc < 14)
                stage(sm + ((kc + 2) % 3) * KCB, g_w + (kc + 2) * KCB, tid);

            // B fragments from h (b = bt*8+gid, k pairs at kc*16+tig*2, +8)
            u32 Bh[4][2];
#pragma unroll
            for (int bt = 0; bt < 4; bt++) {
                int ha = (bt * 8 + gid) * 528 + kc * 32 + tig * 4;
                Bh[bt][0] = *(u32*)(sm + OFF_H + ha);
                Bh[bt][1] = *(u32*)(sm + OFF_H + ha + 16);
            }
            const char* cur = sm + (kc % 3) * KCB;
#pragma unroll
            for (int g = 0; g < 3; g++)
#pragma unroll
                for (int i = 0; i < 2; i++) {
                    int rt = g * 16 + w * 2 + i;
                    const char* ab = cur + rt * 512 + lane * 16;
                    uint4 Ah = *(const uint4*)ab;
                    uint4 Al = *(const uint4*)(ab + IMGHALF);
#pragma unroll
                    for (int bt = 0; bt < 4; bt++) {
                        mma_h(acc[g][i][bt], (u32*)&Ah, Bh[bt]);
                        mma_h(acc[g][i][bt], (u32*)&Al, Bh[bt]);
                    }
                }
        }
        __syncthreads();      // all reads of h/stages done before epilogue

        if (step < 64) {
#pragma unroll
            for (int i = 0; i < 2; i++)
#pragma unroll
                for (int bt = 0; bt < 4; bt++)
#pragma unroll
                    for (int eu = 0; eu < 2; eu++)
#pragma unroll
                        for (int eb = 0; eb < 2; eb++) {
                            int di = eu * 2 + eb;
                            int u = w * 32 + i * 16 + gid + eu * 8;
                            int b = bt * 8 + tig * 2 + eb;
                            float x = xs[step * 32 + b];
                            float r = fsig(acc[0][i][bt][di] +
                                           fmaf(x, pu[u], pbi[u] + pbh[u]));
                            float z = fsig(acc[1][i][bt][di] +
                                           fmaf(x, pu[256 + u],
                                                pbi[256 + u] + pbh[256 + u]));
                            float n = ftanh(fmaf(x, pu[512 + u], pbi[512 + u]) +
                                            r * (acc[2][i][bt][di] + pbh[512 + u]));
                            float hn = fmaf(z, h[i][bt][di] - n, n);
                            h[i][bt][di] = hn;
                            *(__half*)(sm + OFF_H + b * 528 + u * 2) =
                                __float2half_rn(hn);
                            acc[0][i][bt][di] = 0.f;
                            acc[1][i][bt][di] = 0.f;
                            acc[2][i][bt][di] = 0.f;
                        }
        } else {   // gh_dec: write gh + hidden to scratch
#pragma unroll
            for (int i = 0; i < 2; i++)
#pragma unroll
                for (int bt = 0; bt < 4; bt++)
#pragma unroll
                    for (int eu = 0; eu < 2; eu++)
#pragma unroll
                        for (int eb = 0; eb < 2; eb++) {
                            int di = eu * 2 + eb;
                            int u = w * 32 + i * 16 + gid + eu * 8;
                            int b = bt * 8 + tig * 2 + eb;
                            float* gg = g_gh + (size_t)(gb0 + b) * 768;
                            gg[u]       = acc[0][i][bt][di] + pbh[u];
                            gg[256 + u] = acc[1][i][bt][di] + pbh[256 + u];
                            gg[512 + u] = acc[2][i][bt][di] + pbh[512 + u];
                            g_hid[(size_t)(gb0 + b) * 256 + u] = h[i][bt][di];
                        }
        }
    }
}

// ---------- decoder: TL cheap steps, state in registers ----------
__global__ __launch_bounds__(256, 1)
void dec_kernel(const float* __restrict__ w_ih, const float* __restrict__ b_ih,
                const float* __restrict__ w_out, const float* __restrict__ b_out,
                float* __restrict__ out, int TL) {
    __shared__ float red[32 * 264];
    __shared__ float red2[256];
    __shared__ float outs[32];
    const int u = threadIdx.x;
    const int gb0 = blockIdx.x * 32;
    const float u_r = w_ih[u], u_z = w_ih[256 + u], u_n = w_ih[512 + u];
    const float bir = b_ih[u], biz = b_ih[256 + u], bin = b_ih[512 + u];
    const float wo = w_out[u], bo = b_out[0];

    float ghr[32], ghz[32], ghn[32], hid[32], ht[32];
#pragma unroll
    for (int b = 0; b < 32; b++) {
        const float* gg = g_gh + (size_t)(gb0 + b) * 768;
        ghr[b] = gg[u]; ghz[b] = gg[256 + u]; ghn[b] = gg[512 + u];
        hid[b] = g_hid[(size_t)(gb0 + b) * 256 + u];
        ht[b] = hid[b];
    }
#pragma unroll 1
    for (int t = 0; t < TL; t++) {
#pragma unroll
        for (int b = 0; b < 32; b++) red[b * 264 + u] = wo * ht[b];
        __syncthreads();
        {
            int b2 = u >> 3, seg = u & 7;
            float s = 0.f;
#pragma unroll
            for (int j = 0; j < 32; j++)
                s += red[b2 * 264 + seg * 32 + ((j + seg * 4) & 31)];
            red2[u] = s;
        }
        __syncthreads();
        if (u < 32) {
            float s = 0.f;
#pragma unroll
            for (int j = 0; j < 8; j++) s += red2[u * 8 + j];
            s += bo;
            outs[u] = s;
            out[(size_t)(gb0 + u) * TL + t] = s;
        }
        __syncthreads();
#pragma unroll
        for (int b = 0; b < 32; b++) {
            float x = outs[b];
            float r = fsig(fmaf(x, u_r, bir) + ghr[b]);
            float z = fsig(fmaf(x, u_z, biz) + ghz[b]);
            float n = ftanh(fmaf(x, u_n, bin) + r * ghn[b]);
            ht[b] = fmaf(z, hid[b] - n, n);
        }
        __syncthreads();
    }
}

extern "C" void kernel_launch(void* const* d_in, const int* in_sizes, int n_in,
                              void* d_out, int out_size) {
    const float* x     = (const float*)d_in[0];
    const float* w_ih  = (const float*)d_in[1];
    const float* w_hh  = (const float*)d_in[2];
    const float* b_ih  = (const float*)d_in[3];
    const float* b_hh  = (const float*)d_in[4];
    const float* w_out = (const float*)d_in[5];
    const float* b_out = (const float*)d_in[6];
    float* out = (float*)d_out;

    int B  = in_sizes[0] / SEQ;
    int TL = out_size / B;

    prep_kernel<<<768, 256>>>(w_hh);
    cudaFuncSetAttribute(enc_kernel, cudaFuncAttributeMaxDynamicSharedMemorySize,
                         SMEM_ENC);
    enc_kernel<<<B / TB, 256, SMEM_ENC>>>(x, w_ih, b_ih, b_hh);
    dec_kernel<<<B / 32, 256>>>(w_ih, b_ih, w_out, b_out, out, TL);
}

// round 11
// speedup vs baseline: 4.7217x; 1.5336x over previous
#include <cuda_runtime.h>
#include <cuda_fp16.h>
#include <cstdint>

typedef uint32_t u32;

#define SEQ 64
#define TB  32
#define KCB 24576          // staged bytes per k16-chunk (single fp16 image)

__device__ char  g_w[16 * KCB];          // [kc][48 tiles][32 thr][16B]
__device__ float g_gh[4096 * 768];
__device__ float g_hid[4096 * 256];

// ---------- MUFU activations (cheaper than FFMA chain at 2 warps/SMSP) ------
__device__ __forceinline__ float sigf(float v) {
    return __fdividef(1.0f, 1.0f + __expf(-v));
}
__device__ __forceinline__ float tanhf2(float v) {
    return fmaf(2.0f, sigf(2.0f * v), -1.0f);
}

__device__ __forceinline__ void mma_h(float* d, const u32* a, const u32* b) {
    asm volatile(
        "mma.sync.aligned.m16n8k16.row.col.f32.f16.f16.f32 "
        "{%0,%1,%2,%3}, {%4,%5,%6,%7}, {%8,%9}, {%0,%1,%2,%3};"
        : "+f"(d[0]), "+f"(d[1]), "+f"(d[2]), "+f"(d[3])
        : "r"(a[0]), "r"(a[1]), "r"(a[2]), "r"(a[3]), "r"(b[0]), "r"(b[1]));
}

// ---------- prep: w_hh -> fp16 fragment-direct layout ----------
__global__ void prep_kernel(const float* __restrict__ w_hh) {
    int idx = blockIdx.x * 256 + threadIdx.x;
    if (idx >= 768 * 256) return;
    int row = idx >> 8, col = idx & 255;
    __half hv = __float2half_rn(w_hh[idx]);
    int kc = col >> 4, ci = col & 15, rt = row >> 4, ri = row & 15;
    int gid = ri & 7, e = ci & 1, tig = (ci >> 1) & 3;
    int reg = (ri >> 3) | (((ci >> 3) & 1) << 1);
    int off = kc * KCB + rt * 512 + (gid * 4 + tig) * 16 + reg * 4 + e * 2;
    *(__half*)(g_w + off) = hv;
}

// ---------- encoder ----------
// smem: 3 x 24576 stages | h 32x264 fp16 | xs 64x32 f32 | params
#define OFF_H   73728
#define OFF_XS  90624
#define OFF_PU  98816
#define OFF_PBI 101888
#define OFF_PBH 104960
#define SMEM_ENC 108032

__device__ __forceinline__ void stage(char* dst, const char* src, int tid) {
#pragma unroll
    for (int r = 0; r < 6; r++) {
        int off = (tid + r * 256) * 16;
        u32 d = (u32)__cvta_generic_to_shared(dst + off);
        asm volatile("cp.async.cg.shared.global [%0], [%1], 16;"
                     :: "r"(d), "l"(src + off));
    }
    asm volatile("cp.async.commit_group;");
}

__global__ __launch_bounds__(256, 1)
void enc_kernel(const float* __restrict__ gx, const float* __restrict__ w_ih,
                const float* __restrict__ b_ih, const float* __restrict__ b_hh) {
    extern __shared__ char sm[];
    const int tid = threadIdx.x, w = tid >> 5, lane = tid & 31;
    const int gid = lane >> 2, tig = lane & 3;
    const int gb0 = blockIdx.x * TB;
    float* xs  = (float*)(sm + OFF_XS);
    float* pu  = (float*)(sm + OFF_PU);
    float* pbi = (float*)(sm + OFF_PBI);
    float* pbh = (float*)(sm + OFF_PBH);

    for (int i = tid; i < 768; i += 256) {
        pu[i] = w_ih[i]; pbi[i] = b_ih[i]; pbh[i] = b_hh[i];
    }
    for (int i = tid; i < 4224; i += 256) ((u32*)(sm + OFF_H))[i] = 0;
    for (int i = tid; i < TB * SEQ; i += 256) {
        int b = i & 31, t = i >> 5;
        xs[t * 32 + b] = gx[(gb0 + b) * SEQ + t];
    }
    __syncthreads();

    float h[2][4][4];
    float acc[3][2][4][4];
#pragma unroll
    for (int i = 0; i < 2; i++)
#pragma unroll
        for (int bt = 0; bt < 4; bt++)
#pragma unroll
            for (int e = 0; e < 4; e++) {
                h[i][bt][e] = 0.f;
                acc[0][i][bt][e] = acc[1][i][bt][e] = acc[2][i][bt][e] = 0.f;
            }

#pragma unroll 1
    for (int step = 0; step <= 64; step++) {
        stage(sm, g_w, tid);
        stage(sm + KCB, g_w + KCB, tid);
#pragma unroll 1
        for (int kc = 0; kc < 16; kc++) {
            if (kc < 15) asm volatile("cp.async.wait_group 1;");
            else         asm volatile("cp.async.wait_group 0;");
            __syncthreads();              // chunk kc visible; kc-1 consumed by all
            if (kc < 14)
                stage(sm + ((kc + 2) % 3) * KCB, g_w + (kc + 2) * KCB, tid);

            // B fragments from h (b = bt*8+gid, k pairs at kc*16+tig*2, +8)
            u32 Bh[4][2];
#pragma unroll
            for (int bt = 0; bt < 4; bt++) {
                int ha = (bt * 8 + gid) * 528 + kc * 32 + tig * 4;
                Bh[bt][0] = *(u32*)(sm + OFF_H + ha);
                Bh[bt][1] = *(u32*)(sm + OFF_H + ha + 16);
            }
            const char* cur = sm + (kc % 3) * KCB;
#pragma unroll
            for (int g = 0; g < 3; g++)
#pragma unroll
                for (int i = 0; i < 2; i++) {
                    int rt = g * 16 + w * 2 + i;
                    uint4 Ah = *(const uint4*)(cur + rt * 512 + lane * 16);
#pragma unroll
                    for (int bt = 0; bt < 4; bt++)
                        mma_h(acc[g][i][bt], (u32*)&Ah, Bh[bt]);
                }
        }
        __syncthreads();      // all reads of h/stages done before epilogue

        if (step < 64) {
#pragma unroll
            for (int i = 0; i < 2; i++)
#pragma unroll
                for (int bt = 0; bt < 4; bt++)
#pragma unroll
                    for (int eu = 0; eu < 2; eu++)
#pragma unroll
                        for (int eb = 0; eb < 2; eb++) {
                            int di = eu * 2 + eb;
                            int u = w * 32 + i * 16 + gid + eu * 8;
                            int b = bt * 8 + tig * 2 + eb;
                            float x = xs[step * 32 + b];
                            float r = sigf(acc[0][i][bt][di] +
                                           fmaf(x, pu[u], pbi[u] + pbh[u]));
                            float z = sigf(acc[1][i][bt][di] +
                                           fmaf(x, pu[256 + u],
                                                pbi[256 + u] + pbh[256 + u]));
                            float n = tanhf2(fmaf(x, pu[512 + u], pbi[512 + u]) +
                                             r * (acc[2][i][bt][di] + pbh[512 + u]));
                            float hn = fmaf(z, h[i][bt][di] - n, n);
                            h[i][bt][di] = hn;
                            *(__half*)(sm + OFF_H + b * 528 + u * 2) =
                                __float2half_rn(hn);
                            acc[0][i][bt][di] = 0.f;
                            acc[1][i][bt][di] = 0.f;
                            acc[2][i][bt][di] = 0.f;
                        }
        } else {   // gh_dec: write gh + hidden to scratch
#pragma unroll
            for (int i = 0; i < 2; i++)
#pragma unroll
                for (int bt = 0; bt < 4; bt++)
#pragma unroll
                    for (int eu = 0; eu < 2; eu++)
#pragma unroll
                        for (int eb = 0; eb < 2; eb++) {
                            int di = eu * 2 + eb;
                            int u = w * 32 + i * 16 + gid + eu * 8;
                            int b = bt * 8 + tig * 2 + eb;
                            float* gg = g_gh + (size_t)(gb0 + b) * 768;
                            gg[u]       = acc[0][i][bt][di] + pbh[u];
                            gg[256 + u] = acc[1][i][bt][di] + pbh[256 + u];
                            gg[512 + u] = acc[2][i][bt][di] + pbh[512 + u];
                            g_hid[(size_t)(gb0 + b) * 256 + u] = h[i][bt][di];
                        }
        }
    }
}

// ---------- decoder: TL cheap steps, state in registers ----------
__global__ __launch_bounds__(256, 1)
void dec_kernel(const float* __restrict__ w_ih, const float* __restrict__ b_ih,
                const float* __restrict__ w_out, const float* __restrict__ b_out,
                float* __restrict__ out, int TL) {
    __shared__ float red[32 * 264];
    __shared__ float red2[256];
    __shared__ float outs[32];
    const int u = threadIdx.x;
    const int gb0 = blockIdx.x * 32;
    const float u_r = w_ih[u], u_z = w_ih[256 + u], u_n = w_ih[512 + u];
    const float bir = b_ih[u], biz = b_ih[256 + u], bin = b_ih[512 + u];
    const float wo = w_out[u], bo = b_out[0];

    float ghr[32], ghz[32], ghn[32], hid[32], ht[32];
#pragma unroll
    for (int b = 0; b < 32; b++) {
        const float* gg = g_gh + (size_t)(gb0 + b) * 768;
        ghr[b] = gg[u]; ghz[b] = gg[256 + u]; ghn[b] = gg[512 + u];
        hid[b] = g_hid[(size_t)(gb0 + b) * 256 + u];
        ht[b] = hid[b];
    }
#pragma unroll 1
    for (int t = 0; t < TL; t++) {
#pragma unroll
        for (int b = 0; b < 32; b++) red[b * 264 + u] = wo * ht[b];
        __syncthreads();
        {
            int b2 = u >> 3, seg = u & 7;
            float s = 0.f;
#pragma unroll
            for (int j = 0; j < 32; j++)
                s += red[b2 * 264 + seg * 32 + ((j + seg * 4) & 31)];
            red2[u] = s;
        }
        __syncthreads();
        if (u < 32) {
            float s = 0.f;
#pragma unroll
            for (int j = 0; j < 8; j++) s += red2[u * 8 + j];
            s += bo;
            outs[u] = s;
            out[(size_t)(gb0 + u) * TL + t] = s;
        }
        __syncthreads();
#pragma unroll
        for (int b = 0; b < 32; b++) {
            float x = outs[b];
            float r = sigf(fmaf(x, u_r, bir) + ghr[b]);
            float z = sigf(fmaf(x, u_z, biz) + ghz[b]);
            float n = tanhf2(fmaf(x, u_n, bin) + r * ghn[b]);
            ht[b] = fmaf(z, hid[b] - n, n);
        }
        __syncthreads();
    }
}

extern "C" void kernel_launch(void* const* d_in, const int* in_sizes, int n_in,
                              void* d_out, int out_size) {
    const float* x     = (const float*)d_in[0];
    const float* w_ih  = (const float*)d_in[1];
    const float* w_hh  = (const float*)d_in[2];
    const float* b_ih  = (const float*)d_in[3];
    const float* b_hh  = (const float*)d_in[4];
    const float* w_out = (const float*)d_in[5];
    const float* b_out = (const float*)d_in[6];
    float* out = (float*)d_out;

    int B  = in_sizes[0] / SEQ;
    int TL = out_size / B;

    prep_kernel<<<768, 256>>>(w_hh);
    cudaFuncSetAttribute(enc_kernel, cudaFuncAttributeMaxDynamicSharedMemorySize,
                         SMEM_ENC);
    enc_kernel<<<B / TB, 256, SMEM_ENC>>>(x, w_ih, b_ih, b_hh);
    dec_kernel<<<B / 32, 256>>>(w_ih, b_ih, w_out, b_out, out, TL);
}

// round 12
// speedup vs baseline: 5.6033x; 1.1867x over previous
#include <cuda_runtime.h>
#include <cuda_fp16.h>
#include <cstdint>

typedef uint32_t u32;

#define SEQ 64
#define TB  32
#define CH  49152          // staged bytes per k32-chunk
#define NCH 8              // chunks per step
#define TOTCH (65 * NCH)

__device__ char  g_w[NCH * CH];          // [k16-chunk][48 tiles][32 thr][16B]
__device__ float g_gh[4096 * 768];
__device__ float g_hid[4096 * 256];

// ---------- activations ----------
__device__ __forceinline__ float sigap(float v) {      // r,z gates: 1 MUFU
    float y;
    asm("tanh.approx.f32 %0, %1;" : "=f"(y) : "f"(0.5f * v));
    return fmaf(0.5f, y, 0.5f);
}
__device__ __forceinline__ float sigf(float v) {       // accurate
    return __fdividef(1.0f, 1.0f + __expf(-v));
}
__device__ __forceinline__ float tanhf2(float v) {     // n gate: accurate
    return fmaf(2.0f, sigf(2.0f * v), -1.0f);
}

__device__ __forceinline__ void mma_h(float* d, const u32* a, const u32* b) {
    asm volatile(
        "mma.sync.aligned.m16n8k16.row.col.f32.f16.f16.f32 "
        "{%0,%1,%2,%3}, {%4,%5,%6,%7}, {%8,%9}, {%0,%1,%2,%3};"
        : "+f"(d[0]), "+f"(d[1]), "+f"(d[2]), "+f"(d[3])
        : "r"(a[0]), "r"(a[1]), "r"(a[2]), "r"(a[3]), "r"(b[0]), "r"(b[1]));
}

// ---------- prep: w_hh -> fp16 fragment-direct layout (k16 granules) ----------
__global__ void prep_kernel(const float* __restrict__ w_hh) {
    int idx = blockIdx.x * 256 + threadIdx.x;
    if (idx >= 768 * 256) return;
    int row = idx >> 8, col = idx & 255;
    __half hv = __float2half_rn(w_hh[idx]);
    int kc = col >> 4, ci = col & 15, rt = row >> 4, ri = row & 15;
    int gid = ri & 7, e = ci & 1, tig = (ci >> 1) & 3;
    int reg = (ri >> 3) | (((ci >> 3) & 1) << 1);
    int off = kc * 24576 + rt * 512 + (gid * 4 + tig) * 16 + reg * 4 + e * 2;
    *(__half*)(g_w + off) = hv;
}

// ---------- encoder ----------
// smem: 3 x 49152 ring | h 32x264 fp16 | xs 64x32 f32 | params
#define OFF_H   147456
#define OFF_XS  164352
#define OFF_PU  172544
#define OFF_PBI 175616
#define OFF_PBH 178688
#define SMEM_ENC 181760

__device__ __forceinline__ void stage(char* dst, const char* src, int tid) {
#pragma unroll
    for (int r = 0; r < 12; r++) {
        int off = (tid + r * 256) * 16;
        u32 d = (u32)__cvta_generic_to_shared(dst + off);
        asm volatile("cp.async.cg.shared.global [%0], [%1], 16;"
                     :: "r"(d), "l"(src + off));
    }
    asm volatile("cp.async.commit_group;");
}

__global__ __launch_bounds__(256, 1)
void enc_kernel(const float* __restrict__ gx, const float* __restrict__ w_ih,
                const float* __restrict__ b_ih, const float* __restrict__ b_hh) {
    extern __shared__ char sm[];
    const int tid = threadIdx.x, w = tid >> 5, lane = tid & 31;
    const int gid = lane >> 2, tig = lane & 3;
    const int gb0 = blockIdx.x * TB;
    float* xs  = (float*)(sm + OFF_XS);
    float* pu  = (float*)(sm + OFF_PU);
    float* pbi = (float*)(sm + OFF_PBI);
    float* pbh = (float*)(sm + OFF_PBH);

    for (int i = tid; i < 768; i += 256) {
        pu[i] = w_ih[i]; pbi[i] = b_ih[i]; pbh[i] = b_hh[i];
    }
    for (int i = tid; i < 4224; i += 256) ((u32*)(sm + OFF_H))[i] = 0;
    for (int i = tid; i < TB * SEQ; i += 256) {
        int b = i & 31, t = i >> 5;
        xs[t * 32 + b] = gx[(gb0 + b) * SEQ + t];
    }
    __syncthreads();

    float h[2][4][4];
    float acc[3][2][4][4];
#pragma unroll
    for (int i = 0; i < 2; i++)
#pragma unroll
        for (int bt = 0; bt < 4; bt++)
#pragma unroll
            for (int e = 0; e < 4; e++) {
                h[i][bt][e] = 0.f;
                acc[0][i][bt][e] = acc[1][i][bt][e] = acc[2][i][bt][e] = 0.f;
            }

    // continuous ring: global chunk g -> slot g%3, prefetch distance 2
    stage(sm + 0 * CH, g_w + 0 * CH, tid);
    stage(sm + 1 * CH, g_w + 1 * CH, tid);

#pragma unroll 1
    for (int step = 0; step <= 64; step++) {
#pragma unroll 1
        for (int c = 0; c < NCH; c++) {
            const int g = step * NCH + c;
            if (g + 2 < TOTCH) asm volatile("cp.async.wait_group 1;");
            else               asm volatile("cp.async.wait_group 0;");
            __syncthreads();      // chunk g visible; slot (g+2)%3 fully consumed
            if (g + 2 < TOTCH)
                stage(sm + ((g + 2) % 3) * CH, g_w + ((g + 2) & 7) * CH, tid);

            const char* cur = sm + (g % 3) * CH;
#pragma unroll
            for (int sub = 0; sub < 2; sub++) {
                const int kc16 = c * 2 + sub;
                u32 Bh[4][2];
#pragma unroll
                for (int bt = 0; bt < 4; bt++) {
                    int ha = (bt * 8 + gid) * 528 + kc16 * 32 + tig * 4;
                    Bh[bt][0] = *(u32*)(sm + OFF_H + ha);
                    Bh[bt][1] = *(u32*)(sm + OFF_H + ha + 16);
                }
                const char* img = cur + sub * 24576;
#pragma unroll
                for (int gg = 0; gg < 3; gg++)
#pragma unroll
                    for (int i = 0; i < 2; i++) {
                        int rt = gg * 16 + w * 2 + i;
                        uint4 Ah = *(const uint4*)(img + rt * 512 + lane * 16);
#pragma unroll
                        for (int bt = 0; bt < 4; bt++)
                            mma_h(acc[gg][i][bt], (u32*)&Ah, Bh[bt]);
                    }
            }
        }
        __syncthreads();      // last chunk's B reads done before h rewrite

        if (step < 64) {
#pragma unroll
            for (int i = 0; i < 2; i++)
#pragma unroll
                for (int bt = 0; bt < 4; bt++)
#pragma unroll
                    for (int eu = 0; eu < 2; eu++)
#pragma unroll
                        for (int eb = 0; eb < 2; eb++) {
                            int di = eu * 2 + eb;
                            int u = w * 32 + i * 16 + gid + eu * 8;
                            int b = bt * 8 + tig * 2 + eb;
                            float x = xs[step * 32 + b];
                            float r = sigap(acc[0][i][bt][di] +
                                            fmaf(x, pu[u], pbi[u] + pbh[u]));
                            float z = sigap(acc[1][i][bt][di] +
                                            fmaf(x, pu[256 + u],
                                                 pbi[256 + u] + pbh[256 + u]));
                            float n = tanhf2(fmaf(x, pu[512 + u], pbi[512 + u]) +
                                             r * (acc[2][i][bt][di] + pbh[512 + u]));
                            float hn = fmaf(z, h[i][bt][di] - n, n);
                            h[i][bt][di] = hn;
                            *(__half*)(sm + OFF_H + b * 528 + u * 2) =
                                __float2half_rn(hn);
                            acc[0][i][bt][di] = 0.f;
                            acc[1][i][bt][di] = 0.f;
                            acc[2][i][bt][di] = 0.f;
                        }
            // h visibility for next step: ordered by chunk-0 __syncthreads
        } else {   // gh_dec: write gh + hidden to scratch
#pragma unroll
            for (int i = 0; i < 2; i++)
#pragma unroll
                for (int bt = 0; bt < 4; bt++)
#pragma unroll
                    for (int eu = 0; eu < 2; eu++)
#pragma unroll
                        for (int eb = 0; eb < 2; eb++) {
                            int di = eu * 2 + eb;
                            int u = w * 32 + i * 16 + gid + eu * 8;
                            int b = bt * 8 + tig * 2 + eb;
                            float* gg2 = g_gh + (size_t)(gb0 + b) * 768;
                            gg2[u]       = acc[0][i][bt][di] + pbh[u];
                            gg2[256 + u] = acc[1][i][bt][di] + pbh[256 + u];
                            gg2[512 + u] = acc[2][i][bt][di] + pbh[512 + u];
                            g_hid[(size_t)(gb0 + b) * 256 + u] = h[i][bt][di];
                        }
        }
    }
}

// ---------- decoder: TL cheap steps, state in registers ----------
__global__ __launch_bounds__(256, 1)
void dec_kernel(const float* __restrict__ w_ih, const float* __restrict__ b_ih,
                const float* __restrict__ w_out, const float* __restrict__ b_out,
                float* __restrict__ out, int TL) {
    __shared__ float red[32 * 264];
    __shared__ float red2[256];
    __shared__ float outs[32];
    const int u = threadIdx.x;
    const int gb0 = blockIdx.x * 32;
    const float u_r = w_ih[u], u_z = w_ih[256 + u], u_n = w_ih[512 + u];
    const float bir = b_ih[u], biz = b_ih[256 + u], bin = b_ih[512 + u];
    const float wo = w_out[u], bo = b_out[0];

    float ghr[32], ghz[32], ghn[32], hid[32], ht[32];
#pragma unroll
    for (int b = 0; b < 32; b++) {
        const float* gg = g_gh + (size_t)(gb0 + b) * 768;
        ghr[b] = gg[u]; ghz[b] = gg[256 + u]; ghn[b] = gg[512 + u];
        hid[b] = g_hid[(size_t)(gb0 + b) * 256 + u];
        ht[b] = hid[b];
    }
#pragma unroll 1
    for (int t = 0; t < TL; t++) {
#pragma unroll
        for (int b = 0; b < 32; b++) red[b * 264 + u] = wo * ht[b];
        __syncthreads();
        {
            int b2 = u >> 3, seg = u & 7;
            float s = 0.f;
#pragma unroll
            for (int j = 0; j < 32; j++)
                s += red[b2 * 264 + seg * 32 + ((j + seg * 4) & 31)];
            red2[u] = s;
        }
        __syncthreads();
        if (u < 32) {
            float s = 0.f;
#pragma unroll
            for (int j = 0; j < 8; j++) s += red2[u * 8 + j];
            s += bo;
            outs[u] = s;
            out[(size_t)(gb0 + u) * TL + t] = s;
        }
        __syncthreads();
#pragma unroll
        for (int b = 0; b < 32; b++) {
            float x = outs[b];
            float r = sigap(fmaf(x, u_r, bir) + ghr[b]);
            float z = sigap(fmaf(x, u_z, biz) + ghz[b]);
            float n = tanhf2(fmaf(x, u_n, bin) + r * ghn[b]);
            ht[b] = fmaf(z, hid[b] - n, n);
        }
        __syncthreads();
    }
}

extern "C" void kernel_launch(void* const* d_in, const int* in_sizes, int n_in,
                              void* d_out, int out_size) {
    const float* x     = (const float*)d_in[0];
    const float* w_ih  = (const float*)d_in[1];
    const float* w_hh  = (const float*)d_in[2];
    const float* b_ih  = (const float*)d_in[3];
    const float* b_hh  = (const float*)d_in[4];
    const float* w_out = (const float*)d_in[5];
    const float* b_out = (const float*)d_in[6];
    float* out = (float*)d_out;

    int B  = in_sizes[0] / SEQ;
    int TL = out_size / B;

    prep_kernel<<<768, 256>>>(w_hh);
    cudaFuncSetAttribute(enc_kernel, cudaFuncAttributeMaxDynamicSharedMemorySize,
                         SMEM_ENC);
    enc_kernel<<<B / TB, 256, SMEM_ENC>>>(x, w_ih, b_ih, b_hh);
    dec_kernel<<<B / 32, 256>>>(w_ih, b_ih, w_out, b_out, out, TL);
}

// round 14
// speedup vs baseline: 6.4366x; 1.1487x over previous
#include <cuda_runtime.h>
#include <cuda_fp16.h>
#include <cstdint>

typedef uint32_t u32;

#define SEQ 64
#define TB  32
#define CH  49152          // bytes per k32 chunk (all warps)
#define WCH 6144           // per-warp bytes per k32 chunk
#define NCH 8              // chunks per step
#define TOT (65 * NCH)

__device__ char  g_w[NCH * CH];    // [kc32][warp][sub][lt][lane][16B]
__device__ float g_gh[4096 * 768];
__device__ float g_hid[4096 * 256];

// ---------- activations ----------
__device__ __forceinline__ float sigap(float v) {      // r,z gates: 1 MUFU
    float y;
    asm("tanh.approx.f32 %0, %1;" : "=f"(y) : "f"(0.5f * v));
    return fmaf(0.5f, y, 0.5f);
}
__device__ __forceinline__ float sigf(float v) {
    return __fdividef(1.0f, 1.0f + __expf(-v));
}
__device__ __forceinline__ float tanhf2(float v) {     // n gate: accurate
    return fmaf(2.0f, sigf(2.0f * v), -1.0f);
}

__device__ __forceinline__ void mma_h(float* d, const u32* a, const u32* b) {
    asm volatile(
        "mma.sync.aligned.m16n8k16.row.col.f32.f16.f16.f32 "
        "{%0,%1,%2,%3}, {%4,%5,%6,%7}, {%8,%9}, {%0,%1,%2,%3};"
        : "+f"(d[0]), "+f"(d[1]), "+f"(d[2]), "+f"(d[3])
        : "r"(a[0]), "r"(a[1]), "r"(a[2]), "r"(a[3]), "r"(b[0]), "r"(b[1]));
}

// ---------- prep: w_hh -> per-warp fragment-direct layout ----------
// row tile rt = gg*16 + w*2 + i  (gg=gate, w=warp, i=sub-tile)
__global__ void prep_kernel(const float* __restrict__ w_hh) {
    int idx = blockIdx.x * 256 + threadIdx.x;
    if (idx >= 768 * 256) return;
    int row = idx >> 8, col = idx & 255;
    __half hv = __float2half_rn(w_hh[idx]);
    int rt = row >> 4, ri = row & 15;
    int gg = rt >> 4, w = (rt & 15) >> 1, i = rt & 1, lt = gg * 2 + i;
    int kc32 = col >> 5, sub = (col >> 4) & 1, ci = col & 15;
    int gid = ri & 7, e = ci & 1, tig = (ci >> 1) & 3;
    int reg = (ri >> 3) | (((ci >> 3) & 1) << 1);
    int off = kc32 * CH + w * WCH + sub * 3072 + lt * 512 +
              (gid * 4 + tig) * 16 + reg * 4 + e * 2;
    *(__half*)(g_w + off) = hv;
}

// ---------- encoder ----------
// smem: 3 x 49152 ring | h0 32x264 fp16 | h1 | xs 64x32 f32 | params
#define OFF_H0  147456
#define OFF_H1  164352
#define OFF_XS  181248
#define OFF_PU  189440
#define OFF_PBI 192512
#define OFF_PBH 195584
#define SMEM_ENC 198656

// per-warp stage: 12 x 16B, each lane stages exactly what it later reads
__device__ __forceinline__ void stage_w(char* sm, int g, int w, int lane) {
    char* dst = sm + (g % 3) * CH + w * WCH;
    const char* src = g_w + (g & 7) * CH + w * WCH;
#pragma unroll
    for (int r = 0; r < 12; r++) {
        int off = (lane + r * 32) * 16;
        u32 d = (u32)__cvta_generic_to_shared(dst + off);
        asm volatile("cp.async.cg.shared.global [%0], [%1], 16;"
                     :: "r"(d), "l"(src + off));
    }
    asm volatile("cp.async.commit_group;");
}

__global__ __launch_bounds__(256, 1)
void enc_kernel(const float* __restrict__ gx, const float* __restrict__ w_ih,
                const float* __restrict__ b_ih, const float* __restrict__ b_hh) {
    extern __shared__ char sm[];
    const int tid = threadIdx.x, w = tid >> 5, lane = tid & 31;
    const int gid = lane >> 2, tig = lane & 3;
    const int gb0 = blockIdx.x * TB;
    float* xs  = (float*)(sm + OFF_XS);
    float* pu  = (float*)(sm + OFF_PU);
    float* pbi = (float*)(sm + OFF_PBI);
    float* pbh = (float*)(sm + OFF_PBH);

    for (int i = tid; i < 768; i += 256) {
        pu[i] = w_ih[i]; pbi[i] = b_ih[i]; pbh[i] = b_hh[i];
    }
    for (int i = tid; i < 4224; i += 256) ((u32*)(sm + OFF_H0))[i] = 0;
    for (int i = tid; i < TB * SEQ; i += 256) {
        int b = i & 31, t = i >> 5;
        xs[t * 32 + b] = gx[(gb0 + b) * SEQ + t];
    }
    __syncthreads();

    float h[2][4][4];
    float acc[3][2][4][4];
#pragma unroll
    for (int i = 0; i < 2; i++)
#pragma unroll
        for (int bt = 0; bt < 4; bt++)
#pragma unroll
            for (int e = 0; e < 4; e++) {
                h[i][bt][e] = 0.f;
                acc[0][i][bt][e] = acc[1][i][bt][e] = acc[2][i][bt][e] = 0.f;
            }

    // private per-warp ring, prefetch distance 2
    stage_w(sm, 0, w, lane);
    stage_w(sm, 1, w, lane);

#pragma unroll 1
    for (int step = 0; step <= 64; step++) {
        const char* hb = sm + ((step & 1) ? OFF_H1 : OFF_H0);
#pragma unroll 1
        for (int c = 0; c < NCH; c++) {
            const int g = step * NCH + c;
            if (g + 1 < TOT) asm volatile("cp.async.wait_group 1;");
            else             asm volatile("cp.async.wait_group 0;");
            if (g + 2 < TOT) stage_w(sm, g + 2, w, lane);   // slot of g-1

            const char* wslot = sm + (g % 3) * CH + w * WCH;
#pragma unroll
            for (int sub = 0; sub < 2; sub++) {
                const int kc16 = c * 2 + sub;
                u32 Bh[4][2];
#pragma unroll
                for (int bt = 0; bt < 4; bt++) {
                    int ha = (bt * 8 + gid) * 528 + kc16 * 32 + tig * 4;
                    Bh[bt][0] = *(u32*)(hb + ha);
                    Bh[bt][1] = *(u32*)(hb + ha + 16);
                }
                const char* img = wslot + sub * 3072;
#pragma unroll
                for (int gg = 0; gg < 3; gg++)
#pragma unroll
                    for (int i = 0; i < 2; i++) {
                        uint4 Ah = *(const uint4*)(img + (gg * 2 + i) * 512 +
                                                   lane * 16);
#pragma unroll
                        for (int bt = 0; bt < 4; bt++)
                            mma_h(acc[gg][i][bt], (u32*)&Ah, Bh[bt]);
                    }
            }
        }

        if (step < 64) {
            char* hw = sm + ((step & 1) ? OFF_H0 : OFF_H1);   // write other buf
#pragma unroll
            for (int i = 0; i < 2; i++)
#pragma unroll
                for (int bt = 0; bt < 4; bt++)
#pragma unroll
                    for (int eu = 0; eu < 2; eu++)
#pragma unroll
                        for (int eb = 0; eb < 2; eb++) {
                            int di = eu * 2 + eb;
                            int u = w * 32 + i * 16 + gid + eu * 8;
                            int b = bt * 8 + tig * 2 + eb;
                            float x = xs[step * 32 + b];
                            float r = sigap(acc[0][i][bt][di] +
                                            fmaf(x, pu[u], pbi[u] + pbh[u]));
                            float z = sigap(acc[1][i][bt][di] +
                                            fmaf(x, pu[256 + u],
                                                 pbi[256 + u] + pbh[256 + u]));
                            float n = tanhf2(fmaf(x, pu[512 + u], pbi[512 + u]) +
                                             r * (acc[2][i][bt][di] + pbh[512 + u]));
                            float hn = fmaf(z, h[i][bt][di] - n, n);
                            h[i][bt][di] = hn;
                            *(__half*)(hw + b * 528 + u * 2) = __float2half_rn(hn);
                            acc[0][i][bt][di] = 0.f;
                            acc[1][i][bt][di] = 0.f;
                            acc[2][i][bt][di] = 0.f;
                        }
            __syncthreads();   // h writes visible before next step's B reads
        } else {   // gh_dec: write gh + hidden to scratch
#pragma unroll
            for (int i = 0; i < 2; i++)
#pragma unroll
                for (int bt = 0; bt < 4; bt++)
#pragma unroll
                    for (int eu = 0; eu < 2; eu++)
#pragma unroll
                        for (int eb = 0; eb < 2; eb++) {
                            int di = eu * 2 + eb;
                            int u = w * 32 + i * 16 + gid + eu * 8;
                            int b = bt * 8 + tig * 2 + eb;
                            float* gg2 = g_gh + (size_t)(gb0 + b) * 768;
                            gg2[u]       = acc[0][i][bt][di] + pbh[u];
                            gg2[256 + u] = acc[1][i][bt][di] + pbh[256 + u];
                            gg2[512 + u] = acc[2][i][bt][di] + pbh[512 + u];
                            g_hid[(size_t)(gb0 + b) * 256 + u] = h[i][bt][di];
                        }
        }
    }
}

// ---------- decoder: TL cheap steps, state in registers ----------
__global__ __launch_bounds__(256, 1)
void dec_kernel(const float* __restrict__ w_ih, const float* __restrict__ b_ih,
                const float* __restrict__ w_out, const float* __restrict__ b_out,
                float* __restrict__ out, int TL) {
    __shared__ float red[32 * 264];
    __shared__ float red2[256];
    __shared__ float outs[32];
    const int u = threadIdx.x;
    const int gb0 = blockIdx.x * 32;
    const float u_r = w_ih[u], u_z = w_ih[256 + u], u_n = w_ih[512 + u];
    const float bir = b_ih[u], biz = b_ih[256 + u], bin = b_ih[512 + u];
    const float wo = w_out[u], bo = b_out[0];

    float ghr[32], ghz[32], ghn[32], hid[32], ht[32];
#pragma unroll
    for (int b = 0; b < 32; b++) {
        const float* gg = g_gh + (size_t)(gb0 + b) * 768;
        ghr[b] = gg[u]; ghz[b] = gg[256 + u]; ghn[b] = gg[512 + u];
        hid[b] = g_hid[(size_t)(gb0 + b) * 256 + u];
        ht[b] = hid[b];
    }
#pragma unroll 1
    for (int t = 0; t < TL; t++) {
#pragma unroll
        for (int b = 0; b < 32; b++) red[b * 264 + u] = wo * ht[b];
        __syncthreads();
        {
            int b2 = u >> 3, seg = u & 7;
            float s = 0.f;
#pragma unroll
            for (int j = 0; j < 32; j++)
                s += red[b2 * 264 + seg * 32 + ((j + seg * 4) & 31)];
            red2[u] = s;
        }
        __syncthreads();
        if (u < 32) {
            float s = 0.f;
#pragma unroll
            for (int j = 0; j < 8; j++) s += red2[u * 8 + j];
            s += bo;
            outs[u] = s;
            out[(size_t)(gb0 + u) * TL + t] = s;
        }
        __syncthreads();
#pragma unroll
        for (int b = 0; b < 32; b++) {
            float x = outs[b];
            float r = sigap(fmaf(x, u_r, bir) + ghr[b]);
            float z = sigap(fmaf(x, u_z, biz) + ghz[b]);
            float n = tanhf2(fmaf(x, u_n, bin) + r * ghn[b]);
            ht[b] = fmaf(z, hid[b] - n, n);
        }
        __syncthreads();
    }
}

extern "C" void kernel_launch(void* const* d_in, const int* in_sizes, int n_in,
                              void* d_out, int out_size) {
    const float* x     = (const float*)d_in[0];
    const float* w_ih  = (const float*)d_in[1];
    const float* w_hh  = (const float*)d_in[2];
    const float* b_ih  = (const float*)d_in[3];
    const float* b_hh  = (const float*)d_in[4];
    const float* w_out = (const float*)d_in[5];
    const float* b_out = (const float*)d_in[6];
    float* out = (float*)d_out;

    int B  = in_sizes[0] / SEQ;
    int TL = out_size / B;

    prep_kernel<<<768, 256>>>(w_hh);
    cudaFuncSetAttribute(enc_kernel, cudaFuncAttributeMaxDynamicSharedMemorySize,
                         SMEM_ENC);
    enc_kernel<<<B / TB, 256, SMEM_ENC>>>(x, w_ih, b_ih, b_hh);
    dec_kernel<<<B / 32, 256>>>(w_ih, b_ih, w_out, b_out, out, TL);
}

// round 15
// speedup vs baseline: 7.7636x; 1.2062x over previous
#include <cuda_runtime.h>
#include <cuda_fp16.h>
#include <cstdint>

typedef uint32_t u32;

#define SEQ 64
#define TB  32
#define CH  49152          // bytes per k32 chunk (all warps)
#define WCH 6144           // per-warp bytes per k32 chunk
#define NCH 8              // chunks per step
#define TOT (65 * NCH)

__device__ char  g_w[NCH * CH];    // [kc32][warp][sub][lt][lane][16B]
__device__ float g_gh[4096 * 768];
__device__ float g_hid[4096 * 256];

// ---------- activations ----------
__device__ __forceinline__ float sigap(float v) {      // 1 MUFU
    float y;
    asm("tanh.approx.f32 %0, %1;" : "=f"(y) : "f"(0.5f * v));
    return fmaf(0.5f, y, 0.5f);
}
__device__ __forceinline__ float tanap(float v) {      // 1 MUFU
    float y;
    asm("tanh.approx.f32 %0, %1;" : "=f"(y) : "f"(v));
    return y;
}

__device__ __forceinline__ void mma_h(float* d, const u32* a, const u32* b) {
    asm volatile(
        "mma.sync.aligned.m16n8k16.row.col.f32.f16.f16.f32 "
        "{%0,%1,%2,%3}, {%4,%5,%6,%7}, {%8,%9}, {%0,%1,%2,%3};"
        : "+f"(d[0]), "+f"(d[1]), "+f"(d[2]), "+f"(d[3])
        : "r"(a[0]), "r"(a[1]), "r"(a[2]), "r"(a[3]), "r"(b[0]), "r"(b[1]));
}

// ---------- prep: w_hh -> per-warp fragment-direct layout ----------
__global__ void prep_kernel(const float* __restrict__ w_hh) {
    int idx = blockIdx.x * 256 + threadIdx.x;
    if (idx >= 768 * 256) return;
    int row = idx >> 8, col = idx & 255;
    __half hv = __float2half_rn(w_hh[idx]);
    int rt = row >> 4, ri = row & 15;
    int gg = rt >> 4, w = (rt & 15) >> 1, i = rt & 1, lt = gg * 2 + i;
    int kc32 = col >> 5, sub = (col >> 4) & 1, ci = col & 15;
    int gid = ri & 7, e = ci & 1, tig = (ci >> 1) & 3;
    int reg = (ri >> 3) | (((ci >> 3) & 1) << 1);
    int off = kc32 * CH + w * WCH + sub * 3072 + lt * 512 +
              (gid * 4 + tig) * 16 + reg * 4 + e * 2;
    *(__half*)(g_w + off) = hv;
}

// ---------- encoder ----------
// smem: 3 x 49152 ring | h0 32x264 fp16 | h1 | xs 64x32 f32 | params
#define OFF_H0  147456
#define OFF_H1  164352
#define OFF_XS  181248
#define OFF_PU  189440
#define OFF_PBI 192512
#define OFF_PBH 195584
#define SMEM_ENC 198656

__device__ __forceinline__ void stage_w(char* sm, int g, int w, int lane) {
    char* dst = sm + (g % 3) * CH + w * WCH;
    const char* src = g_w + (g & 7) * CH + w * WCH;
#pragma unroll
    for (int r = 0; r < 12; r++) {
        int off = (lane + r * 32) * 16;
        u32 d = (u32)__cvta_generic_to_shared(dst + off);
        asm volatile("cp.async.cg.shared.global [%0], [%1], 16;"
                     :: "r"(d), "l"(src + off));
    }
    asm volatile("cp.async.commit_group;");
}

__global__ __launch_bounds__(256, 1)
void enc_kernel(const float* __restrict__ gx, const float* __restrict__ w_ih,
                const float* __restrict__ b_ih, const float* __restrict__ b_hh) {
    extern __shared__ char sm[];
    const int tid = threadIdx.x, w = tid >> 5, lane = tid & 31;
    const int gid = lane >> 2, tig = lane & 3;
    const int gb0 = blockIdx.x * TB;
    float* xs  = (float*)(sm + OFF_XS);
    float* pu  = (float*)(sm + OFF_PU);
    float* pbi = (float*)(sm + OFF_PBI);
    float* pbh = (float*)(sm + OFF_PBH);

    for (int i = tid; i < 768; i += 256) {
        pu[i] = w_ih[i]; pbi[i] = b_ih[i]; pbh[i] = b_hh[i];
    }
    for (int i = tid; i < 4224; i += 256) ((u32*)(sm + OFF_H0))[i] = 0;
    for (int i = tid; i < TB * SEQ; i += 256) {
        int b = i & 31, t = i >> 5;
        xs[t * 32 + b] = gx[(gb0 + b) * SEQ + t];
    }
    __syncthreads();

    float h[2][4][4];
    float acc[3][2][4][4];
#pragma unroll
    for (int i = 0; i < 2; i++)
#pragma unroll
        for (int bt = 0; bt < 4; bt++)
#pragma unroll
            for (int e = 0; e < 4; e++) {
                h[i][bt][e] = 0.f;
                acc[0][i][bt][e] = acc[1][i][bt][e] = acc[2][i][bt][e] = 0.f;
            }

    stage_w(sm, 0, w, lane);
    stage_w(sm, 1, w, lane);

#pragma unroll 1
    for (int step = 0; step <= 64; step++) {
        const char* hb = sm + ((step & 1) ? OFF_H1 : OFF_H0);
#pragma unroll 1
        for (int c = 0; c < NCH; c++) {
            const int g = step * NCH + c;
            if (g + 1 < TOT) asm volatile("cp.async.wait_group 1;");
            else             asm volatile("cp.async.wait_group 0;");
            if (g + 2 < TOT) stage_w(sm, g + 2, w, lane);

            const char* wslot = sm + (g % 3) * CH + w * WCH;
#pragma unroll
            for (int sub = 0; sub < 2; sub++) {
                const int kc16 = c * 2 + sub;
                u32 Bh[4][2];
#pragma unroll
                for (int bt = 0; bt < 4; bt++) {
                    int ha = (bt * 8 + gid) * 528 + kc16 * 32 + tig * 4;
                    Bh[bt][0] = *(u32*)(hb + ha);
                    Bh[bt][1] = *(u32*)(hb + ha + 16);
                }
                const char* img = wslot + sub * 3072;
#pragma unroll
                for (int gg = 0; gg < 3; gg++)
#pragma unroll
                    for (int i = 0; i < 2; i++) {
                        uint4 Ah = *(const uint4*)(img + (gg * 2 + i) * 512 +
                                                   lane * 16);
#pragma unroll
                        for (int bt = 0; bt < 4; bt++)
                            mma_h(acc[gg][i][bt], (u32*)&Ah, Bh[bt]);
                    }
            }
        }

        if (step < 64) {
            char* hw = sm + ((step & 1) ? OFF_H0 : OFF_H1);
#pragma unroll
            for (int i = 0; i < 2; i++)
#pragma unroll
                for (int bt = 0; bt < 4; bt++)
#pragma unroll
                    for (int eu = 0; eu < 2; eu++)
#pragma unroll
                        for (int eb = 0; eb < 2; eb++) {
                            int di = eu * 2 + eb;
                            int u = w * 32 + i * 16 + gid + eu * 8;
                            int b = bt * 8 + tig * 2 + eb;
                            float x = xs[step * 32 + b];
                            float r = sigap(acc[0][i][bt][di] +
                                            fmaf(x, pu[u], pbi[u] + pbh[u]));
                            float z = sigap(acc[1][i][bt][di] +
                                            fmaf(x, pu[256 + u],
                                                 pbi[256 + u] + pbh[256 + u]));
                            float n = tanap(fmaf(x, pu[512 + u], pbi[512 + u]) +
                                            r * (acc[2][i][bt][di] + pbh[512 + u]));
                            float hn = fmaf(z, h[i][bt][di] - n, n);
                            h[i][bt][di] = hn;
                            *(__half*)(hw + b * 528 + u * 2) = __float2half_rn(hn);
                            acc[0][i][bt][di] = 0.f;
                            acc[1][i][bt][di] = 0.f;
                            acc[2][i][bt][di] = 0.f;
                        }
            __syncthreads();   // h writes visible before next step's B reads
        } else {
#pragma unroll
            for (int i = 0; i < 2; i++)
#pragma unroll
                for (int bt = 0; bt < 4; bt++)
#pragma unroll
                    for (int eu = 0; eu < 2; eu++)
#pragma unroll
                        for (int eb = 0; eb < 2; eb++) {
                            int di = eu * 2 + eb;
                            int u = w * 32 + i * 16 + gid + eu * 8;
                            int b = bt * 8 + tig * 2 + eb;
                            float* gg2 = g_gh + (size_t)(gb0 + b) * 768;
                            gg2[u]       = acc[0][i][bt][di] + pbh[u];
                            gg2[256 + u] = acc[1][i][bt][di] + pbh[256 + u];
                            gg2[512 + u] = acc[2][i][bt][di] + pbh[512 + u];
                            g_hid[(size_t)(gb0 + b) * 256 + u] = h[i][bt][di];
                        }
        }
    }
}

// ---------- decoder: warp-local, zero barriers ----------
// warp owns 2 batches; lane owns units u = lane + 32j, j=0..7.
__global__ __launch_bounds__(256, 1)
void dec_kernel(const float* __restrict__ w_ih, const float* __restrict__ b_ih,
                const float* __restrict__ w_out, const float* __restrict__ b_out,
                float* __restrict__ out, int TL) {
    const int w = threadIdx.x >> 5, lane = threadIdx.x & 31;
    const int b0 = blockIdx.x * 16 + w * 2;

    float wo[8], ur[8], uz[8], un[8], bir[8], biz[8], bin[8];
#pragma unroll
    for (int j = 0; j < 8; j++) {
        int u = lane + 32 * j;
        wo[j] = w_out[u];
        ur[j] = w_ih[u]; uz[j] = w_ih[256 + u]; un[j] = w_ih[512 + u];
        bir[j] = b_ih[u]; biz[j] = b_ih[256 + u]; bin[j] = b_ih[512 + u];
    }
    float ghr[2][8], ghz[2][8], ghn[2][8], hid[2][8], ht[2][8];
#pragma unroll
    for (int bb = 0; bb < 2; bb++) {
        const float* gg = g_gh + (size_t)(b0 + bb) * 768;
        const float* hh = g_hid + (size_t)(b0 + bb) * 256;
#pragma unroll
        for (int j = 0; j < 8; j++) {
            int u = lane + 32 * j;
            ghr[bb][j] = gg[u]; ghz[bb][j] = gg[256 + u]; ghn[bb][j] = gg[512 + u];
            hid[bb][j] = hh[u]; ht[bb][j] = hh[u];
        }
    }
    const float bo = b_out[0];

#pragma unroll 1
    for (int t = 0; t < TL; t++) {
#pragma unroll
        for (int bb = 0; bb < 2; bb++) {
            float p = 0.f;
#pragma unroll
            for (int j = 0; j < 8; j++) p = fmaf(wo[j], ht[bb][j], p);
#pragma unroll
            for (int o = 16; o > 0; o >>= 1)
                p += __shfl_xor_sync(0xFFFFFFFFu, p, o);
            float x = p + bo;
            if (lane == 0) out[(size_t)(b0 + bb) * TL + t] = x;
#pragma unroll
            for (int j = 0; j < 8; j++) {
                float r = sigap(fmaf(x, ur[j], bir[j]) + ghr[bb][j]);
                float z = sigap(fmaf(x, uz[j], biz[j]) + ghz[bb][j]);
                float n = tanap(fmaf(x, un[j], bin[j]) + r * ghn[bb][j]);
                ht[bb][j] = fmaf(z, hid[bb][j] - n, n);
            }
        }
    }
}

extern "C" void kernel_launch(void* const* d_in, const int* in_sizes, int n_in,
                              void* d_out, int out_size) {
    const float* x     = (const float*)d_in[0];
    const float* w_ih  = (const float*)d_in[1];
    const float* w_hh  = (const float*)d_in[2];
    const float* b_ih  = (const float*)d_in[3];
    const float* b_hh  = (const float*)d_in[4];
    const float* w_out = (const float*)d_in[5];
    const float* b_out = (const float*)d_in[6];
    float* out = (float*)d_out;

    int B  = in_sizes[0] / SEQ;
    int TL = out_size / B;

    prep_kernel<<<768, 256>>>(w_hh);
    cudaFuncSetAttribute(enc_kernel, cudaFuncAttributeMaxDynamicSharedMemorySize,
                         SMEM_ENC);
    enc_kernel<<<B / TB, 256, SMEM_ENC>>>(x, w_ih, b_ih, b_hh);
    dec_kernel<<<B / 16, 256>>>(w_ih, b_ih, w_out, b_out, out, TL);
}

// round 16
// speedup vs baseline: 7.9757x; 1.0273x over previous
#include <cuda_runtime.h>
#include <cuda_fp16.h>
#include <cstdint>

typedef uint32_t u32;

#define SEQ 64
#define TB  32
#define CH  49152          // bytes per k32 chunk (all warps)
#define WCH 6144           // per-warp bytes per k32 chunk
#define NCH 8              // chunks per GEMM
#define TOT (64 * NCH)     // 63 encoder GEMMs + gh_dec (step-0 GEMM skipped)

__device__ char g_w[NCH * CH];     // [kc32][warp][sub][lt][lane][16B]

// ---------- activations ----------
__device__ __forceinline__ float sigap(float v) {
    float y;
    asm("tanh.approx.f32 %0, %1;" : "=f"(y) : "f"(0.5f * v));
    return fmaf(0.5f, y, 0.5f);
}
__device__ __forceinline__ float tanap(float v) {
    float y;
    asm("tanh.approx.f32 %0, %1;" : "=f"(y) : "f"(v));
    return y;
}

__device__ __forceinline__ void mma_h(float* d, const u32* a, const u32* b) {
    asm volatile(
        "mma.sync.aligned.m16n8k16.row.col.f32.f16.f16.f32 "
        "{%0,%1,%2,%3}, {%4,%5,%6,%7}, {%8,%9}, {%0,%1,%2,%3};"
        : "+f"(d[0]), "+f"(d[1]), "+f"(d[2]), "+f"(d[3])
        : "r"(a[0]), "r"(a[1]), "r"(a[2]), "r"(a[3]), "r"(b[0]), "r"(b[1]));
}

// ---------- prep: w_hh -> per-warp fragment-direct layout ----------
__global__ void prep_kernel(const float* __restrict__ w_hh) {
    int idx = blockIdx.x * 256 + threadIdx.x;
    if (idx >= 768 * 256) return;
    int row = idx >> 8, col = idx & 255;
    __half hv = __float2half_rn(w_hh[idx]);
    int rt = row >> 4, ri = row & 15;
    int gg = rt >> 4, w = (rt & 15) >> 1, i = rt & 1, lt = gg * 2 + i;
    int kc32 = col >> 5, sub = (col >> 4) & 1, ci = col & 15;
    int gid = ri & 7, e = ci & 1, tig = (ci >> 1) & 3;
    int reg = (ri >> 3) | (((ci >> 3) & 1) << 1);
    int off = kc32 * CH + w * WCH + sub * 3072 + lt * 512 +
              (gid * 4 + tig) * 16 + reg * 4 + e * 2;
    *(__half*)(g_w + off) = hv;
}

// ---------- fused encoder + decoder ----------
// smem: 3 x 49152 ring (decoder overlays DR/DZ/DN/DH here) | h0 | h1 | xs | params
#define OFF_H0  147456
#define OFF_H1  164352
#define OFF_XS  181248
#define OFF_PU  189440
#define OFF_PBI 192512
#define OFF_PBH 195584
#define SMEM_ENC 198656
// decoder transpose overlays (float indices into sm base)
#define DRF 0
#define DZF 8448
#define DNF 16896
#define DHF 25344

__device__ __forceinline__ void stage_w(char* sm, int g, int w, int lane) {
    char* dst = sm + (g % 3) * CH + w * WCH;
    const char* src = g_w + (g & 7) * CH + w * WCH;
#pragma unroll
    for (int r = 0; r < 12; r++) {
        int off = (lane + r * 32) * 16;
        u32 d = (u32)__cvta_generic_to_shared(dst + off);
        asm volatile("cp.async.cg.shared.global [%0], [%1], 16;"
                     :: "r"(d), "l"(src + off));
    }
    asm volatile("cp.async.commit_group;");
}

__global__ __launch_bounds__(256, 1)
void gru_kernel(const float* __restrict__ gx, const float* __restrict__ w_ih,
                const float* __restrict__ b_ih, const float* __restrict__ b_hh,
                const float* __restrict__ w_out, const float* __restrict__ b_out,
                float* __restrict__ out, int TL) {
    extern __shared__ char sm[];
    const int tid = threadIdx.x, w = tid >> 5, lane = tid & 31;
    const int gid = lane >> 2, tig = lane & 3;
    const int gb0 = blockIdx.x * TB;
    float* smf = (float*)sm;
    float* xs  = (float*)(sm + OFF_XS);
    float* pu  = (float*)(sm + OFF_PU);
    float* pbi = (float*)(sm + OFF_PBI);
    float* pbh = (float*)(sm + OFF_PBH);

    for (int i = tid; i < 768; i += 256) {
        pu[i] = w_ih[i]; pbi[i] = b_ih[i]; pbh[i] = b_hh[i];
    }
    for (int i = tid; i < TB * SEQ; i += 256) {
        int b = i & 31, t = i >> 5;
        xs[t * 32 + b] = gx[(gb0 + b) * SEQ + t];
    }
    __syncthreads();

    float h[2][4][4];
    float acc[3][2][4][4];
#pragma unroll
    for (int i = 0; i < 2; i++)
#pragma unroll
        for (int bt = 0; bt < 4; bt++)
#pragma unroll
            for (int e = 0; e < 4; e++) {
                h[i][bt][e] = 0.f;
                acc[0][i][bt][e] = acc[1][i][bt][e] = acc[2][i][bt][e] = 0.f;
            }

    stage_w(sm, 0, w, lane);
    stage_w(sm, 1, w, lane);

#pragma unroll 1
    for (int step = 0; step <= 64; step++) {
        // step 0: h=0 -> GEMM result is exactly 0; skip it (acc already 0)
        if (step >= 1) {
            const char* hb = sm + ((step & 1) ? OFF_H1 : OFF_H0);
#pragma unroll 1
            for (int c = 0; c < NCH; c++) {
                const int g = (step - 1) * NCH + c;
                if (g + 1 < TOT) asm volatile("cp.async.wait_group 1;");
                else             asm volatile("cp.async.wait_group 0;");
                if (g + 2 < TOT) stage_w(sm, g + 2, w, lane);

                const char* wslot = sm + (g % 3) * CH + w * WCH;
#pragma unroll
                for (int sub = 0; sub < 2; sub++) {
                    const int kc16 = c * 2 + sub;
                    u32 Bh[4][2];
#pragma unroll
                    for (int bt = 0; bt < 4; bt++) {
                        int ha = (bt * 8 + gid) * 528 + kc16 * 32 + tig * 4;
                        Bh[bt][0] = *(u32*)(hb + ha);
                        Bh[bt][1] = *(u32*)(hb + ha + 16);
                    }
                    const char* img = wslot + sub * 3072;
#pragma unroll
                    for (int gg = 0; gg < 3; gg++)
#pragma unroll
                        for (int i = 0; i < 2; i++) {
                            uint4 Ah = *(const uint4*)(img + (gg * 2 + i) * 512 +
                                                       lane * 16);
#pragma unroll
                            for (int bt = 0; bt < 4; bt++)
                                mma_h(acc[gg][i][bt], (u32*)&Ah, Bh[bt]);
                        }
                }
            }
        }

        if (step < 64) {
            char* hw = sm + ((step & 1) ? OFF_H0 : OFF_H1);
#pragma unroll
            for (int i = 0; i < 2; i++)
#pragma unroll
                for (int bt = 0; bt < 4; bt++)
#pragma unroll
                    for (int eu = 0; eu < 2; eu++)
#pragma unroll
                        for (int eb = 0; eb < 2; eb++) {
                            int di = eu * 2 + eb;
                            int u = w * 32 + i * 16 + gid + eu * 8;
                            int b = bt * 8 + tig * 2 + eb;
                            float x = xs[step * 32 + b];
                            float r = sigap(acc[0][i][bt][di] +
                                            fmaf(x, pu[u], pbi[u] + pbh[u]));
                            float z = sigap(acc[1][i][bt][di] +
                                            fmaf(x, pu[256 + u],
                                                 pbi[256 + u] + pbh[256 + u]));
                            float n = tanap(fmaf(x, pu[512 + u], pbi[512 + u]) +
                                            r * (acc[2][i][bt][di] + pbh[512 + u]));
                            float hn = fmaf(z, h[i][bt][di] - n, n);
                            h[i][bt][di] = hn;
                            *(__half*)(hw + b * 528 + u * 2) = __float2half_rn(hn);
                            acc[0][i][bt][di] = 0.f;
                            acc[1][i][bt][di] = 0.f;
                            acc[2][i][bt][di] = 0.f;
                        }
            __syncthreads();   // h writes visible before next step's B reads
        }
    }

    // ---- transpose gh_dec + hidden into ring smem for warp-local decode ----
    __syncthreads();           // all warps done reading the ring
#pragma unroll
    for (int i = 0; i < 2; i++)
#pragma unroll
        for (int bt = 0; bt < 4; bt++)
#pragma unroll
            for (int eu = 0; eu < 2; eu++)
#pragma unroll
                for (int eb = 0; eb < 2; eb++) {
                    int di = eu * 2 + eb;
                    int u = w * 32 + i * 16 + gid + eu * 8;
                    int b = bt * 8 + tig * 2 + eb;
                    smf[DRF + b * 264 + u] = acc[0][i][bt][di] + pbh[u];
                    smf[DZF + b * 264 + u] = acc[1][i][bt][di] + pbh[256 + u];
                    smf[DNF + b * 264 + u] = acc[2][i][bt][di] + pbh[512 + u];
                    smf[DHF + b * 264 + u] = h[i][bt][di];
                }
    __syncthreads();

    // ---- decode: warp owns 4 batches, lane owns units u = lane+32j ----
    const int b0l = w * 4;
    float wo[8], urh[8], uzh[8], un[8], bin[8];
#pragma unroll
    for (int j = 0; j < 8; j++) {
        int u = lane + 32 * j;
        wo[j]  = w_out[u];
        urh[j] = 0.5f * pu[u];
        uzh[j] = 0.5f * pu[256 + u];
        un[j]  = pu[512 + u];
        bin[j] = pbi[512 + u];
    }
    float crh[4][8], czh[4][8], ht[4][8];
#pragma unroll
    for (int bb = 0; bb < 4; bb++)
#pragma unroll
        for (int j = 0; j < 8; j++) {
            int u = lane + 32 * j, b = b0l + bb;
            crh[bb][j] = 0.5f * (pbi[u] + smf[DRF + b * 264 + u]);
            czh[bb][j] = 0.5f * (pbi[256 + u] + smf[DZF + b * 264 + u]);
            ht[bb][j]  = smf[DHF + b * 264 + u];
        }
    const float bo = b_out[0];

#pragma unroll 1
    for (int t = 0; t < TL; t++) {
#pragma unroll
        for (int bb = 0; bb < 4; bb++) {
            float p = 0.f;
#pragma unroll
            for (int j = 0; j < 8; j++) p = fmaf(wo[j], ht[bb][j], p);
#pragma unroll
            for (int o = 16; o > 0; o >>= 1)
                p += __shfl_xor_sync(0xFFFFFFFFu, p, o);
            float x = p + bo;
            if (lane == 0) out[(size_t)(gb0 + b0l + bb) * TL + t] = x;
            int b = b0l + bb;
#pragma unroll
            for (int j = 0; j < 8; j++) {
                int u = lane + 32 * j;
                float rt2 = tanap(fmaf(x, urh[j], crh[bb][j]));
                float r   = fmaf(0.5f, rt2, 0.5f);
                float zt  = tanap(fmaf(x, uzh[j], czh[bb][j]));
                float ghn = smf[DNF + b * 264 + u];
                float hid = smf[DHF + b * 264 + u];
                float n   = tanap(fmaf(r, ghn, fmaf(x, un[j], bin[j])));
                float d   = hid - n;
                float e   = fmaf(zt, d, d);         // d*(1+zt)
                ht[bb][j] = fmaf(0.5f, e, n);       // n + z*(hid-n)
            }
        }
    }
}

extern "C" void kernel_launch(void* const* d_in, const int* in_sizes, int n_in,
                              void* d_out, int out_size) {
    const float* x     = (const float*)d_in[0];
    const float* w_ih  = (const float*)d_in[1];
    const float* w_hh  = (const float*)d_in[2];
    const float* b_ih  = (const float*)d_in[3];
    const float* b_hh  = (const float*)d_in[4];
    const float* w_out = (const float*)d_in[5];
    const float* b_out = (const float*)d_in[6];
    float* out = (float*)d_out;

    int B  = in_sizes[0] / SEQ;
    int TL = out_size / B;

    prep_kernel<<<768, 256>>>(w_hh);
    cudaFuncSetAttribute(gru_kernel, cudaFuncAttributeMaxDynamicSharedMemorySize,
                         SMEM_ENC);
    gru_kernel<<<B / TB, 256, SMEM_ENC>>>(x, w_ih, b_ih, b_hh, w_out, b_out,
                                          out, TL);
}

// round 17
// speedup vs baseline: 8.5088x; 1.0668x over previous
#include <cuda_runtime.h>
#include <cuda_fp16.h>
#include <cstdint>

typedef uint32_t u32;

#define SEQ 64
#define TB  32
#define CH  49152          // bytes per k32 chunk (all warps)
#define WCH 3072           // per-warp bytes per k32 chunk (16 warps)
#define NCH 8              // chunks per GEMM
#define TOT (64 * NCH)     // 63 encoder GEMMs + gh_dec (step-0 GEMM skipped)
#define NTH 512

__device__ char g_w[NCH * CH];     // [kc32][warp16][sub][gate][512B frag]

// ---------- activations ----------
__device__ __forceinline__ float sigap(float v) {
    float y;
    asm("tanh.approx.f32 %0, %1;" : "=f"(y) : "f"(0.5f * v));
    return fmaf(0.5f, y, 0.5f);
}
__device__ __forceinline__ float tanap(float v) {
    float y;
    asm("tanh.approx.f32 %0, %1;" : "=f"(y) : "f"(v));
    return y;
}

__device__ __forceinline__ void mma_h(float* d, const u32* a, const u32* b) {
    asm volatile(
        "mma.sync.aligned.m16n8k16.row.col.f32.f16.f16.f32 "
        "{%0,%1,%2,%3}, {%4,%5,%6,%7}, {%8,%9}, {%0,%1,%2,%3};"
        : "+f"(d[0]), "+f"(d[1]), "+f"(d[2]), "+f"(d[3])
        : "r"(a[0]), "r"(a[1]), "r"(a[2]), "r"(a[3]), "r"(b[0]), "r"(b[1]));
}

// ---------- prep: w_hh -> 16-warp fragment-direct layout ----------
// rt = gg*16 + wp*2 + ii ; owning warp w = ii*8 + wp
__global__ void prep_kernel(const float* __restrict__ w_hh) {
    int idx = blockIdx.x * 256 + threadIdx.x;
    if (idx >= 768 * 256) return;
    int row = idx >> 8, col = idx & 255;
    __half hv = __float2half_rn(w_hh[idx]);
    int rt = row >> 4, ri = row & 15;
    int gg = rt >> 4, wp = (rt & 15) >> 1, ii = rt & 1;
    int w = ii * 8 + wp;
    int kc32 = col >> 5, sub = (col >> 4) & 1, ci = col & 15;
    int gid = ri & 7, e = ci & 1, tig = (ci >> 1) & 3;
    int reg = (ri >> 3) | (((ci >> 3) & 1) << 1);
    int off = kc32 * CH + w * WCH + sub * 1536 + gg * 512 +
              (gid * 4 + tig) * 16 + reg * 4 + e * 2;
    *(__half*)(g_w + off) = hv;
}

// ---------- fused encoder + decoder ----------
// smem: 3 x 49152 ring (decoder overlays here) | h0 | h1 | xs | params
#define OFF_H0  147456
#define OFF_H1  164352
#define OFF_XS  181248
#define OFF_PU  189440
#define OFF_PBI 192512
#define OFF_PBH 195584
#define SMEM_ENC 198656
// decoder transpose overlays (float indices into sm base)
#define DRF 0
#define DZF 8448
#define DNF 16896
#define DHF 25344

__device__ __forceinline__ void stage_w(char* sm, int g, int w, int lane) {
    char* dst = sm + (g % 3) * CH + w * WCH;
    const char* src = g_w + (g & 7) * CH + w * WCH;
#pragma unroll
    for (int r = 0; r < 6; r++) {
        int off = (lane + r * 32) * 16;
        u32 d = (u32)__cvta_generic_to_shared(dst + off);
        asm volatile("cp.async.cg.shared.global [%0], [%1], 16;"
                     :: "r"(d), "l"(src + off));
    }
    asm volatile("cp.async.commit_group;");
}

__global__ __launch_bounds__(NTH, 1)
void gru_kernel(const float* __restrict__ gx, const float* __restrict__ w_ih,
                const float* __restrict__ b_ih, const float* __restrict__ b_hh,
                const float* __restrict__ w_out, const float* __restrict__ b_out,
                float* __restrict__ out, int TL) {
    extern __shared__ char sm[];
    const int tid = threadIdx.x, w = tid >> 5, lane = tid & 31;
    const int wp = w & 7, ii = w >> 3;
    const int gid = lane >> 2, tig = lane & 3;
    const int gb0 = blockIdx.x * TB;
    float* smf = (float*)sm;
    float* xs  = (float*)(sm + OFF_XS);
    float* pu  = (float*)(sm + OFF_PU);
    float* pbi = (float*)(sm + OFF_PBI);
    float* pbh = (float*)(sm + OFF_PBH);

    for (int i = tid; i < 768; i += NTH) {
        pu[i] = w_ih[i]; pbi[i] = b_ih[i]; pbh[i] = b_hh[i];
    }
    for (int i = tid; i < TB * SEQ; i += NTH) {
        int b = i & 31, t = i >> 5;
        xs[t * 32 + b] = gx[(gb0 + b) * SEQ + t];
    }
    __syncthreads();

    float h[4][4];
    float acc[3][4][4];
#pragma unroll
    for (int bt = 0; bt < 4; bt++)
#pragma unroll
        for (int e = 0; e < 4; e++) {
            h[bt][e] = 0.f;
            acc[0][bt][e] = acc[1][bt][e] = acc[2][bt][e] = 0.f;
        }

    stage_w(sm, 0, w, lane);
    stage_w(sm, 1, w, lane);

#pragma unroll 1
    for (int step = 0; step <= 64; step++) {
        // step 0: h=0 -> GEMM result exactly 0; skip (acc already 0)
        if (step >= 1) {
            const char* hb = sm + ((step & 1) ? OFF_H1 : OFF_H0);
#pragma unroll 1
            for (int c = 0; c < NCH; c++) {
                const int g = (step - 1) * NCH + c;
                if (g + 1 < TOT) asm volatile("cp.async.wait_group 1;");
                else             asm volatile("cp.async.wait_group 0;");
                if (g + 2 < TOT) stage_w(sm, g + 2, w, lane);

                const char* wslot = sm + (g % 3) * CH + w * WCH;
#pragma unroll
                for (int sub = 0; sub < 2; sub++) {
                    const int kc16 = c * 2 + sub;
                    u32 Bh[4][2];
#pragma unroll
                    for (int bt = 0; bt < 4; bt++) {
                        int ha = (bt * 8 + gid) * 528 + kc16 * 32 + tig * 4;
                        Bh[bt][0] = *(u32*)(hb + ha);
                        Bh[bt][1] = *(u32*)(hb + ha + 16);
                    }
                    const char* img = wslot + sub * 1536;
#pragma unroll
                    for (int gg = 0; gg < 3; gg++) {
                        uint4 Ah = *(const uint4*)(img + gg * 512 + lane * 16);
#pragma unroll
                        for (int bt = 0; bt < 4; bt++)
                            mma_h(acc[gg][bt], (u32*)&Ah, Bh[bt]);
                    }
                }
            }
        }

        if (step < 64) {
            char* hw = sm + ((step & 1) ? OFF_H0 : OFF_H1);
#pragma unroll
            for (int bt = 0; bt < 4; bt++)
#pragma unroll
                for (int eu = 0; eu < 2; eu++)
#pragma unroll
                    for (int eb = 0; eb < 2; eb++) {
                        int di = eu * 2 + eb;
                        int u = wp * 32 + ii * 16 + gid + eu * 8;
                        int b = bt * 8 + tig * 2 + eb;
                        float x = xs[step * 32 + b];
                        float r = sigap(acc[0][bt][di] +
                                        fmaf(x, pu[u], pbi[u] + pbh[u]));
                        float z = sigap(acc[1][bt][di] +
                                        fmaf(x, pu[256 + u],
                                             pbi[256 + u] + pbh[256 + u]));
                        float n = tanap(fmaf(x, pu[512 + u], pbi[512 + u]) +
                                        r * (acc[2][bt][di] + pbh[512 + u]));
                        float hn = fmaf(z, h[bt][di] - n, n);
                        h[bt][di] = hn;
                        *(__half*)(hw + b * 528 + u * 2) = __float2half_rn(hn);
                        acc[0][bt][di] = 0.f;
                        acc[1][bt][di] = 0.f;
                        acc[2][bt][di] = 0.f;
                    }
            __syncthreads();   // h writes visible before next step's B reads
        }
    }

    // ---- transpose gh_dec + hidden into ring smem for warp-local decode ----
    __syncthreads();           // all warps done reading the ring
#pragma unroll
    for (int bt = 0; bt < 4; bt++)
#pragma unroll
        for (int eu = 0; eu < 2; eu++)
#pragma unroll
            for (int eb = 0; eb < 2; eb++) {
                int di = eu * 2 + eb;
                int u = wp * 32 + ii * 16 + gid + eu * 8;
                int b = bt * 8 + tig * 2 + eb;
                smf[DRF + b * 264 + u] = acc[0][bt][di] + pbh[u];
                smf[DZF + b * 264 + u] = acc[1][bt][di] + pbh[256 + u];
                smf[DNF + b * 264 + u] = acc[2][bt][di] + pbh[512 + u];
                smf[DHF + b * 264 + u] = h[bt][di];
            }
    __syncthreads();

    // ---- decode: warp owns 2 batches, lane owns units u = lane+32j ----
    const int b0l = w * 2;
    float wo[8], urh[8], uzh[8], un[8], bin[8];
#pragma unroll
    for (int j = 0; j < 8; j++) {
        int u = lane + 32 * j;
        wo[j]  = w_out[u];
        urh[j] = 0.5f * pu[u];
        uzh[j] = 0.5f * pu[256 + u];
        un[j]  = pu[512 + u];
        bin[j] = pbi[512 + u];
    }
    float crh[2][8], czh[2][8], ht[2][8];
#pragma unroll
    for (int bb = 0; bb < 2; bb++)
#pragma unroll
        for (int j = 0; j < 8; j++) {
            int u = lane + 32 * j, b = b0l + bb;
            crh[bb][j] = 0.5f * (pbi[u] + smf[DRF + b * 264 + u]);
            czh[bb][j] = 0.5f * (pbi[256 + u] + smf[DZF + b * 264 + u]);
            ht[bb][j]  = smf[DHF + b * 264 + u];
        }
    const float bo = b_out[0];

#pragma unroll 1
    for (int t = 0; t < TL; t++) {
#pragma unroll
        for (int bb = 0; bb < 2; bb++) {
            float p = 0.f;
#pragma unroll
            for (int j = 0; j < 8; j++) p = fmaf(wo[j], ht[bb][j], p);
#pragma unroll
            for (int o = 16; o > 0; o >>= 1)
                p += __shfl_xor_sync(0xFFFFFFFFu, p, o);
            float x = p + bo;
            if (lane == 0) out[(size_t)(gb0 + b0l + bb) * TL + t] = x;
            int b = b0l + bb;
#pragma unroll
            for (int j = 0; j < 8; j++) {
                int u = lane + 32 * j;
                float rt2 = tanap(fmaf(x, urh[j], crh[bb][j]));
                float r   = fmaf(0.5f, rt2, 0.5f);
                float zt  = tanap(fmaf(x, uzh[j], czh[bb][j]));
                float ghn = smf[DNF + b * 264 + u];
                float hid = smf[DHF + b * 264 + u];
                float n   = tanap(fmaf(r, ghn, fmaf(x, un[j], bin[j])));
                float d   = hid - n;
                float e   = fmaf(zt, d, d);         // d*(1+zt)
                ht[bb][j] = fmaf(0.5f, e, n);       // n + z*(hid-n)
            }
        }
    }
}

extern "C" void kernel_launch(void* const* d_in, const int* in_sizes, int n_in,
                              void* d_out, int out_size) {
    const float* x     = (const float*)d_in[0];
    const float* w_ih  = (const float*)d_in[1];
    const float* w_hh  = (const float*)d_in[2];
    const float* b_ih  = (const float*)d_in[3];
    const float* b_hh  = (const float*)d_in[4];
    const float* w_out = (const float*)d_in[5];
    const float* b_out = (const float*)d_in[6];
    float* out = (float*)d_out;

    int B  = in_sizes[0] / SEQ;
    int TL = out_size / B;

    prep_kernel<<<768, 256>>>(w_hh);
    cudaFuncSetAttribute(gru_kernel, cudaFuncAttributeMaxDynamicSharedMemorySize,
                         SMEM_ENC);
    gru_kernel<<<B / TB, NTH, SMEM_ENC>>>(x, w_ih, b_ih, b_hh, w_out, b_out,
                                          out, TL);
}